// round 2
// baseline (speedup 1.0000x reference)
#include <cuda_runtime.h>
#include <cstdint>

// Problem constants (from reference setup_inputs)
#define NN 50000
#define EE 800000
#define F1 256      // input features / layer1 hidden (H*C = 8*32)
#define H1 8
#define F2 64       // layer2 output

// ---------------- static scratch (device globals; no runtime alloc) ----------
__device__ float    g_xl1[NN * F1];
__device__ float    g_xr1[NN * F1];
__device__ float    g_aggr1[NN * F1];
__device__ float    g_h1[NN * F1];
__device__ float    g_logits1[(size_t)EE * H1];
__device__ unsigned g_m1[NN * H1];
__device__ float    g_den1[NN * H1];

__device__ float    g_xl2[NN * F2];
__device__ float    g_xr2[NN * F2];
__device__ float    g_aggr2[NN * F2];
__device__ float    g_logits2[EE];
__device__ unsigned g_m2[NN];
__device__ float    g_den2[NN];

// monotone float<->uint encoding for atomicMax on floats
__device__ __forceinline__ unsigned fenc(float f) {
    int i = __float_as_int(f);
    return (unsigned)(i >= 0 ? (i ^ 0x80000000) : ~i);
}
__device__ __forceinline__ float fdec(unsigned u) {
    int i = (u & 0x80000000u) ? (int)(u ^ 0x80000000u) : ~(int)u;
    return __int_as_float(i);
}

// ---------------- init ------------------------------------------------------
__global__ void init_kernel() {
    int i = blockIdx.x * blockDim.x + threadIdx.x;
    int stride = gridDim.x * blockDim.x;
    for (int j = i; j < NN * F1; j += stride) g_aggr1[j] = 0.f;
    for (int j = i; j < NN * F2; j += stride) g_aggr2[j] = 0.f;
    for (int j = i; j < NN * H1; j += stride) { g_m1[j] = 0u; g_den1[j] = 0.f; }
    for (int j = i; j < NN; j += stride)      { g_m2[j] = 0u; g_den2[j] = 0.f; }
}

// ---------------- SGEMM: C[N,M] = A[N,K] @ B[K,M] ---------------------------
// 64x64 tile, BK=16, 256 threads, 4x4 register block per thread.
__global__ void sgemm64(const float* __restrict__ A, const float* __restrict__ B,
                        float* __restrict__ C, int N, int K, int M) {
    __shared__ float As[16][64];
    __shared__ float Bs[16][64];
    int tid = threadIdx.x;
    int tx = tid & 15, ty = tid >> 4;
    int rowBase = blockIdx.y * 64;
    int colBase = blockIdx.x * 64;

    int ar = tid >> 2;          // 0..63 row within A tile
    int ak = (tid & 3) * 4;     // 0,4,8,12 k offset
    int bk = tid >> 4;          // 0..15
    int bc = (tid & 15) * 4;    // 0..60

    float acc[4][4] = {};

    for (int k0 = 0; k0 < K; k0 += 16) {
        float4 av = make_float4(0.f, 0.f, 0.f, 0.f);
        int arow = rowBase + ar;
        if (arow < N)
            av = *(const float4*)(A + (size_t)arow * K + k0 + ak);
        As[ak + 0][ar] = av.x;
        As[ak + 1][ar] = av.y;
        As[ak + 2][ar] = av.z;
        As[ak + 3][ar] = av.w;

        float4 bv = *(const float4*)(B + (size_t)(k0 + bk) * M + colBase + bc);
        *(float4*)&Bs[bk][bc] = bv;
        __syncthreads();

#pragma unroll
        for (int k = 0; k < 16; k++) {
            float4 a4 = *(float4*)&As[k][ty * 4];
            float4 b4 = *(float4*)&Bs[k][tx * 4];
            float a[4] = {a4.x, a4.y, a4.z, a4.w};
            float b[4] = {b4.x, b4.y, b4.z, b4.w};
#pragma unroll
            for (int i = 0; i < 4; i++)
#pragma unroll
                for (int j = 0; j < 4; j++)
                    acc[i][j] += a[i] * b[j];
        }
        __syncthreads();
    }

#pragma unroll
    for (int i = 0; i < 4; i++) {
        int r = rowBase + ty * 4 + i;
        if (r < N) {
#pragma unroll
            for (int j = 0; j < 4; j++)
                C[(size_t)r * M + colBase + tx * 4 + j] = acc[i][j];
        }
    }
}

// ---------------- layer 1 edge kernels --------------------------------------
// one warp per edge; lane = channel within head, loop over 8 heads
__global__ void edge_logits1(const int* __restrict__ ei,
                             const float* __restrict__ att, int E) {
    int w = (int)((blockIdx.x * blockDim.x + threadIdx.x) >> 5);
    int lane = threadIdx.x & 31;
    if (w >= E) return;
    int s = ei[w];
    int d = ei[E + w];
    const float* pl = g_xl1 + (size_t)s * F1;
    const float* pr = g_xr1 + (size_t)d * F1;
#pragma unroll
    for (int h = 0; h < H1; h++) {
        float v = pl[h * 32 + lane] + pr[h * 32 + lane];
        v = v > 0.f ? v : 0.2f * v;
        float p = v * att[h * 32 + lane];
#pragma unroll
        for (int o = 16; o; o >>= 1) p += __shfl_xor_sync(0xFFFFFFFFu, p, o);
        if (lane == 0) {
            g_logits1[(size_t)w * H1 + h] = p;
            atomicMax(&g_m1[d * H1 + h], fenc(p));
        }
    }
}

__global__ void edge_scatter1(const int* __restrict__ ei, int E) {
    int w = (int)((blockIdx.x * blockDim.x + threadIdx.x) >> 5);
    int lane = threadIdx.x & 31;
    if (w >= E) return;
    int s = ei[w];
    int d = ei[E + w];
    float ex = 0.f;
    if (lane < H1) {
        float lg = g_logits1[(size_t)w * H1 + lane];
        float mm = fdec(g_m1[d * H1 + lane]);
        ex = __expf(lg - mm);
        atomicAdd(&g_den1[d * H1 + lane], ex);
    }
    const float* pl = g_xl1 + (size_t)s * F1;
    float* pa = g_aggr1 + (size_t)d * F1;
#pragma unroll
    for (int h = 0; h < H1; h++) {
        float e = __shfl_sync(0xFFFFFFFFu, ex, h);
        atomicAdd(&pa[h * 32 + lane], e * pl[h * 32 + lane]);
    }
}

__global__ void finalize1(const float* __restrict__ b1) {
    int i = blockIdx.x * blockDim.x + threadIdx.x;
    if (i >= NN * F1) return;
    int n = i >> 8;        // /256
    int j = i & 255;
    int h = j >> 5;
    float v = g_aggr1[i] / (g_den1[n * H1 + h] + 1e-16f) + b1[j];
    g_h1[i] = v > 0.f ? v : 0.f;   // relu between layers
}

// ---------------- layer 2 edge kernels (H=1, C=64) --------------------------
__global__ void edge_logits2(const int* __restrict__ ei,
                             const float* __restrict__ att, int E) {
    int w = (int)((blockIdx.x * blockDim.x + threadIdx.x) >> 5);
    int lane = threadIdx.x & 31;
    if (w >= E) return;
    int s = ei[w];
    int d = ei[E + w];
    const float* pl = g_xl2 + (size_t)s * F2;
    const float* pr = g_xr2 + (size_t)d * F2;
    float p = 0.f;
#pragma unroll
    for (int c = lane; c < F2; c += 32) {
        float v = pl[c] + pr[c];
        v = v > 0.f ? v : 0.2f * v;
        p += v * att[c];
    }
#pragma unroll
    for (int o = 16; o; o >>= 1) p += __shfl_xor_sync(0xFFFFFFFFu, p, o);
    if (lane == 0) {
        g_logits2[w] = p;
        atomicMax(&g_m2[d], fenc(p));
    }
}

__global__ void edge_scatter2(const int* __restrict__ ei, int E) {
    int w = (int)((blockIdx.x * blockDim.x + threadIdx.x) >> 5);
    int lane = threadIdx.x & 31;
    if (w >= E) return;
    int s = ei[w];
    int d = ei[E + w];
    float ex = 0.f;
    if (lane == 0) {
        ex = __expf(g_logits2[w] - fdec(g_m2[d]));
        atomicAdd(&g_den2[d], ex);
    }
    ex = __shfl_sync(0xFFFFFFFFu, ex, 0);
    const float* pl = g_xl2 + (size_t)s * F2;
    float* pa = g_aggr2 + (size_t)d * F2;
#pragma unroll
    for (int c = lane; c < F2; c += 32)
        atomicAdd(&pa[c], ex * pl[c]);
}

// one warp per node: bias add + write h, compute log_softmax over 64
__global__ void finalize2(const float* __restrict__ b2, float* __restrict__ out) {
    int n = (int)((blockIdx.x * blockDim.x + threadIdx.x) >> 5);
    int lane = threadIdx.x & 31;
    if (n >= NN) return;
    float den = g_den2[n] + 1e-16f;
    float v0 = g_aggr2[(size_t)n * F2 + lane]      / den + b2[lane];
    float v1 = g_aggr2[(size_t)n * F2 + 32 + lane] / den + b2[32 + lane];
    float mx = fmaxf(v0, v1);
#pragma unroll
    for (int o = 16; o; o >>= 1) mx = fmaxf(mx, __shfl_xor_sync(0xFFFFFFFFu, mx, o));
    float se = __expf(v0 - mx) + __expf(v1 - mx);
#pragma unroll
    for (int o = 16; o; o >>= 1) se += __shfl_xor_sync(0xFFFFFFFFu, se, o);
    float lse = mx + __logf(se);
    out[(size_t)n * F2 + lane]      = v0;
    out[(size_t)n * F2 + 32 + lane] = v1;
    out[(size_t)NN * F2 + (size_t)n * F2 + lane]      = v0 - lse;
    out[(size_t)NN * F2 + (size_t)n * F2 + 32 + lane] = v1 - lse;
}

// ---------------- launch ----------------------------------------------------
extern "C" void kernel_launch(void* const* d_in, const int* in_sizes, int n_in,
                              void* d_out, int out_size) {
    const float* x    = (const float*)d_in[0];
    const int*   ei   = (const int*)d_in[1];     // JAX canonicalizes int64 -> int32
    const float* Wl1  = (const float*)d_in[2];
    const float* Wr1  = (const float*)d_in[3];
    const float* att1 = (const float*)d_in[4];
    const float* b1   = (const float*)d_in[5];
    const float* Wl2  = (const float*)d_in[6];
    const float* Wr2  = (const float*)d_in[7];
    const float* att2 = (const float*)d_in[8];
    const float* b2   = (const float*)d_in[9];
    float* out = (float*)d_out;

    int E = in_sizes[1] / 2;
    if (E > EE) E = EE;
    int N = in_sizes[0] / F1;
    if (N > NN) N = NN;

    // device-global scratch addresses (pure address query; capture-safe, no alloc)
    void *xl1p, *xr1p, *h1p, *xl2p, *xr2p;
    cudaGetSymbolAddress(&xl1p, g_xl1);
    cudaGetSymbolAddress(&xr1p, g_xr1);
    cudaGetSymbolAddress(&h1p,  g_h1);
    cudaGetSymbolAddress(&xl2p, g_xl2);
    cudaGetSymbolAddress(&xr2p, g_xr2);

    init_kernel<<<4096, 256>>>();

    // layer 1 projections: [N,256] @ [256,256]
    dim3 grid1(F1 / 64, (N + 63) / 64);
    sgemm64<<<grid1, 256>>>(x, Wl1, (float*)xl1p, N, F1, F1);
    sgemm64<<<grid1, 256>>>(x, Wr1, (float*)xr1p, N, F1, F1);

    int eblocks = (E + 7) / 8;   // 8 warps / block, 1 warp / edge
    edge_logits1<<<eblocks, 256>>>(ei, att1, E);
    edge_scatter1<<<eblocks, 256>>>(ei, E);
    finalize1<<<(NN * F1 + 255) / 256, 256>>>(b1);

    // layer 2 projections: [N,256] @ [256,64]
    dim3 grid2(F2 / 64, (N + 63) / 64);
    sgemm64<<<grid2, 256>>>((const float*)h1p, Wl2, (float*)xl2p, N, F1, F2);
    sgemm64<<<grid2, 256>>>((const float*)h1p, Wr2, (float*)xr2p, N, F1, F2);

    edge_logits2<<<eblocks, 256>>>(ei, att2, E);
    edge_scatter2<<<eblocks, 256>>>(ei, E);
    finalize2<<<(NN * 32 + 255) / 256, 256>>>(b2, out);

    (void)n_in; (void)out_size;
}

// round 5
// speedup vs baseline: 1.8336x; 1.8336x over previous
#include <cuda_runtime.h>
#include <cstdint>

#define NN 50000
#define EE 800000
#define F1 256      // layer1 hidden (H*C = 8*32)
#define H1 8
#define F2 64       // layer2 output

// ---------------- static scratch ----------
__device__ float g_xl1[NN * F1];
__device__ float g_xr1[NN * F1];
__device__ float g_aggr1[NN * F1];
__device__ float g_h1[NN * F1];
__device__ float g_den1[NN * H1];

__device__ float g_xl2[NN * F2];
__device__ float g_xr2[NN * F2];
__device__ float g_aggr2[NN * F2];
__device__ float g_den2[NN];

__device__ __forceinline__ void red_add_v4(float* p, float4 v) {
    asm volatile("red.global.add.v4.f32 [%0], {%1,%2,%3,%4};"
                 :: "l"(p), "f"(v.x), "f"(v.y), "f"(v.z), "f"(v.w) : "memory");
}
__device__ __forceinline__ void red_add_f32(float* p, float v) {
    asm volatile("red.global.add.f32 [%0], %1;" :: "l"(p), "f"(v) : "memory");
}

// ---------------- init ------------------------------------------------------
__global__ void init_kernel() {
    int i = blockIdx.x * blockDim.x + threadIdx.x;
    int stride = gridDim.x * blockDim.x;
    float4 z = make_float4(0.f, 0.f, 0.f, 0.f);
    for (int j = i; j < NN * F1 / 4; j += stride) ((float4*)g_aggr1)[j] = z;
    for (int j = i; j < NN * F2 / 4; j += stride) ((float4*)g_aggr2)[j] = z;
    for (int j = i; j < NN * H1; j += stride) g_den1[j] = 0.f;
    for (int j = i; j < NN; j += stride)      g_den2[j] = 0.f;
}

// ---------------- SGEMM: C[N,M] = A[N,K] @ B[K,M] ---------------------------
__global__ void sgemm64(const float* __restrict__ A, const float* __restrict__ B,
                        float* __restrict__ C, int N, int K, int M) {
    __shared__ float As[16][64];
    __shared__ float Bs[16][64];
    int tid = threadIdx.x;
    int tx = tid & 15, ty = tid >> 4;
    int rowBase = blockIdx.y * 64;
    int colBase = blockIdx.x * 64;

    int ar = tid >> 2;
    int ak = (tid & 3) * 4;
    int bk = tid >> 4;
    int bc = (tid & 15) * 4;

    float acc[4][4] = {};

    for (int k0 = 0; k0 < K; k0 += 16) {
        float4 av = make_float4(0.f, 0.f, 0.f, 0.f);
        int arow = rowBase + ar;
        if (arow < N)
            av = *(const float4*)(A + (size_t)arow * K + k0 + ak);
        As[ak + 0][ar] = av.x;
        As[ak + 1][ar] = av.y;
        As[ak + 2][ar] = av.z;
        As[ak + 3][ar] = av.w;

        float4 bv = *(const float4*)(B + (size_t)(k0 + bk) * M + colBase + bc);
        *(float4*)&Bs[bk][bc] = bv;
        __syncthreads();

#pragma unroll
        for (int k = 0; k < 16; k++) {
            float4 a4 = *(float4*)&As[k][ty * 4];
            float4 b4 = *(float4*)&Bs[k][tx * 4];
            float a[4] = {a4.x, a4.y, a4.z, a4.w};
            float b[4] = {b4.x, b4.y, b4.z, b4.w};
#pragma unroll
            for (int i = 0; i < 4; i++)
#pragma unroll
                for (int j = 0; j < 4; j++)
                    acc[i][j] += a[i] * b[j];
        }
        __syncthreads();
    }

#pragma unroll
    for (int i = 0; i < 4; i++) {
        int r = rowBase + ty * 4 + i;
        if (r < N) {
#pragma unroll
            for (int j = 0; j < 4; j++)
                C[(size_t)r * M + colBase + tx * 4 + j] = acc[i][j];
        }
    }
}

// ---------------- fused layer-1 edge pass -----------------------------------
// One warp per edge. Channels as float4: lane owns float4 idx {lane, 32+lane}.
// float4 idx i covers channels 4i..4i+3, head = i/8. Lane's two heads:
// h0 = lane/8 (0..3), h1 = 4 + lane/8. 8-lane butterfly leaves every lane
// holding its own head's logit, so the scatter factor is already per-lane.
__global__ void fused_edge1(const int* __restrict__ ei,
                            const float* __restrict__ att, int E) {
    int w = (int)((blockIdx.x * blockDim.x + threadIdx.x) >> 5);
    int lane = threadIdx.x & 31;
    if (w >= E) return;
    int s = ei[w];
    int d = ei[E + w];

    const float4* pl = (const float4*)(g_xl1 + (size_t)s * F1);
    const float4* pr = (const float4*)(g_xr1 + (size_t)d * F1);
    const float4* pa = (const float4*)att;

    float4 a0 = pl[lane],      a1 = pl[32 + lane];
    float4 b0 = pr[lane],      b1 = pr[32 + lane];
    float4 t0 = pa[lane],      t1 = pa[32 + lane];

    float v, p0 = 0.f, p1 = 0.f;
    v = a0.x + b0.x; p0 += (v > 0.f ? v : 0.2f * v) * t0.x;
    v = a0.y + b0.y; p0 += (v > 0.f ? v : 0.2f * v) * t0.y;
    v = a0.z + b0.z; p0 += (v > 0.f ? v : 0.2f * v) * t0.z;
    v = a0.w + b0.w; p0 += (v > 0.f ? v : 0.2f * v) * t0.w;
    v = a1.x + b1.x; p1 += (v > 0.f ? v : 0.2f * v) * t1.x;
    v = a1.y + b1.y; p1 += (v > 0.f ? v : 0.2f * v) * t1.y;
    v = a1.z + b1.z; p1 += (v > 0.f ? v : 0.2f * v) * t1.z;
    v = a1.w + b1.w; p1 += (v > 0.f ? v : 0.2f * v) * t1.w;

    // reduce within 8-lane groups (one group per head-quarter)
#pragma unroll
    for (int o = 1; o < 8; o <<= 1) {
        p0 += __shfl_xor_sync(0xFFFFFFFFu, p0, o);
        p1 += __shfl_xor_sync(0xFFFFFFFFu, p1, o);
    }
    float e0 = __expf(p0);
    float e1 = __expf(p1);

    if ((lane & 7) == 0) {
        int g = lane >> 3;
        red_add_f32(&g_den1[d * H1 + g], e0);
        red_add_f32(&g_den1[d * H1 + 4 + g], e1);
    }

    float* dst = g_aggr1 + (size_t)d * F1;
    red_add_v4(dst + 4 * lane,        make_float4(a0.x * e0, a0.y * e0, a0.z * e0, a0.w * e0));
    red_add_v4(dst + 4 * (32 + lane), make_float4(a1.x * e1, a1.y * e1, a1.z * e1, a1.w * e1));
}

__global__ void finalize1(const float* __restrict__ b1) {
    int i = blockIdx.x * blockDim.x + threadIdx.x;   // float4 index
    if (i >= NN * F1 / 4) return;
    int n = i >> 6;           // /64 float4 per node
    int j4 = i & 63;          // float4 within node
    int h = j4 >> 3;          // head
    float inv = 1.f / (g_den1[n * H1 + h] + 1e-16f);
    float4 a = ((const float4*)g_aggr1)[i];
    float4 bb = ((const float4*)b1)[j4];
    float4 r;
    r.x = fmaxf(a.x * inv + bb.x, 0.f);
    r.y = fmaxf(a.y * inv + bb.y, 0.f);
    r.z = fmaxf(a.z * inv + bb.z, 0.f);
    r.w = fmaxf(a.w * inv + bb.w, 0.f);
    ((float4*)g_h1)[i] = r;
}

// ---------------- fused layer-2 edge pass (H=1, C=64) -----------------------
// Half-warp per edge: 16 lanes * float4 = 64 channels.
__global__ void fused_edge2(const int* __restrict__ ei,
                            const float* __restrict__ att, int E) {
    int w = (int)((blockIdx.x * blockDim.x + threadIdx.x) >> 5);
    int lane = threadIdx.x & 31;
    int e_id = 2 * w + (lane >> 4);
    int l16 = lane & 15;
    if (e_id >= E) return;
    int s = ei[e_id];
    int d = ei[E + e_id];

    const float4* pl = (const float4*)(g_xl2 + (size_t)s * F2);
    const float4* pr = (const float4*)(g_xr2 + (size_t)d * F2);
    float4 a = pl[l16];
    float4 b = pr[l16];
    float4 t = ((const float4*)att)[l16];

    float v, p = 0.f;
    v = a.x + b.x; p += (v > 0.f ? v : 0.2f * v) * t.x;
    v = a.y + b.y; p += (v > 0.f ? v : 0.2f * v) * t.y;
    v = a.z + b.z; p += (v > 0.f ? v : 0.2f * v) * t.z;
    v = a.w + b.w; p += (v > 0.f ? v : 0.2f * v) * t.w;

#pragma unroll
    for (int o = 1; o < 16; o <<= 1) p += __shfl_xor_sync(0xFFFFFFFFu, p, o);
    float e = __expf(p);

    if (l16 == 0) red_add_f32(&g_den2[d], e);
    red_add_v4(g_aggr2 + (size_t)d * F2 + 4 * l16,
               make_float4(a.x * e, a.y * e, a.z * e, a.w * e));
}

// one warp per node: bias add + log_softmax over 64
__global__ void finalize2(const float* __restrict__ b2, float* __restrict__ out) {
    int n = (int)((blockIdx.x * blockDim.x + threadIdx.x) >> 5);
    int lane = threadIdx.x & 31;
    if (n >= NN) return;
    float inv = 1.f / (g_den2[n] + 1e-16f);
    float v0 = g_aggr2[(size_t)n * F2 + lane]      * inv + b2[lane];
    float v1 = g_aggr2[(size_t)n * F2 + 32 + lane] * inv + b2[32 + lane];
    float mx = fmaxf(v0, v1);
#pragma unroll
    for (int o = 16; o; o >>= 1) mx = fmaxf(mx, __shfl_xor_sync(0xFFFFFFFFu, mx, o));
    float se = __expf(v0 - mx) + __expf(v1 - mx);
#pragma unroll
    for (int o = 16; o; o >>= 1) se += __shfl_xor_sync(0xFFFFFFFFu, se, o);
    float lse = mx + __logf(se);
    out[(size_t)n * F2 + lane]      = v0;
    out[(size_t)n * F2 + 32 + lane] = v1;
    out[(size_t)NN * F2 + (size_t)n * F2 + lane]      = v0 - lse;
    out[(size_t)NN * F2 + (size_t)n * F2 + 32 + lane] = v1 - lse;
}

// ---------------- launch ----------------------------------------------------
extern "C" void kernel_launch(void* const* d_in, const int* in_sizes, int n_in,
                              void* d_out, int out_size) {
    const float* x    = (const float*)d_in[0];
    const int*   ei   = (const int*)d_in[1];     // JAX canonicalizes int64 -> int32
    const float* Wl1  = (const float*)d_in[2];
    const float* Wr1  = (const float*)d_in[3];
    const float* att1 = (const float*)d_in[4];
    const float* b1   = (const float*)d_in[5];
    const float* Wl2  = (const float*)d_in[6];
    const float* Wr2  = (const float*)d_in[7];
    const float* att2 = (const float*)d_in[8];
    const float* b2   = (const float*)d_in[9];
    float* out = (float*)d_out;

    int E = in_sizes[1] / 2;
    if (E > EE) E = EE;
    int N = in_sizes[0] / F1;
    if (N > NN) N = NN;

    void *xl1p, *xr1p, *h1p, *xl2p, *xr2p;
    cudaGetSymbolAddress(&xl1p, g_xl1);
    cudaGetSymbolAddress(&xr1p, g_xr1);
    cudaGetSymbolAddress(&h1p,  g_h1);
    cudaGetSymbolAddress(&xl2p, g_xl2);
    cudaGetSymbolAddress(&xr2p, g_xr2);

    init_kernel<<<2048, 256>>>();

    // layer 1 projections: [N,256] @ [256,256]
    dim3 grid1(F1 / 64, (N + 63) / 64);
    sgemm64<<<grid1, 256>>>(x, Wl1, (float*)xl1p, N, F1, F1);
    sgemm64<<<grid1, 256>>>(x, Wr1, (float*)xr1p, N, F1, F1);

    int eblocks1 = (E + 7) / 8;          // 8 warps/block, 1 warp/edge
    fused_edge1<<<eblocks1, 256>>>(ei, att1, E);
    finalize1<<<(NN * F1 / 4 + 255) / 256, 256>>>(b1);

    // layer 2 projections: [N,256] @ [256,64]
    dim3 grid2(F2 / 64, (N + 63) / 64);
    sgemm64<<<grid2, 256>>>((const float*)h1p, Wl2, (float*)xl2p, N, F1, F2);
    sgemm64<<<grid2, 256>>>((const float*)h1p, Wr2, (float*)xr2p, N, F1, F2);

    int eblocks2 = (E + 15) / 16;        // 2 edges/warp
    fused_edge2<<<eblocks2, 256>>>(ei, att2, E);
    finalize2<<<(NN * 32 + 255) / 256, 256>>>(b2, out);

    (void)n_in; (void)out_size;
}

// round 6
// speedup vs baseline: 2.1148x; 1.1533x over previous
#include <cuda_runtime.h>
#include <cstdint>

#define NN 50000
#define EE 800000
#define F1 256      // layer1 hidden (H*C = 8*32)
#define H1 8
#define F2 64       // layer2 output
#define PE1 16      // edges per warp chunk (layer1)
#define PE2 16      // edges per half-warp chunk (layer2)
#define SCAN_B 196  // ceil(50000/256)

// ---------------- static scratch ----------
__device__ float g_xl1[NN * F1];
__device__ float g_xr1[NN * F1];
__device__ float g_aggr1[NN * F1];
__device__ float g_h1[NN * F1];
__device__ float g_den1[NN * H1];

__device__ float g_xl2[NN * F2];
__device__ float g_xr2[NN * F2];
__device__ float g_aggr2[NN * F2];
__device__ float g_den2[NN];

// sort scratch
__device__ int  g_cnt[NN];
__device__ int  g_bsum[SCAN_B];
__device__ int  g_pos[NN];
__device__ int2 g_perm[EE];     // (src, dst) sorted by dst

__device__ __forceinline__ void red_add_v4(float* p, float4 v) {
    asm volatile("red.global.add.v4.f32 [%0], {%1,%2,%3,%4};"
                 :: "l"(p), "f"(v.x), "f"(v.y), "f"(v.z), "f"(v.w) : "memory");
}
__device__ __forceinline__ void red_add_f32(float* p, float v) {
    asm volatile("red.global.add.f32 [%0], %1;" :: "l"(p), "f"(v) : "memory");
}

// ---------------- init ------------------------------------------------------
__global__ void init_kernel() {
    int i = blockIdx.x * blockDim.x + threadIdx.x;
    int stride = gridDim.x * blockDim.x;
    float4 z = make_float4(0.f, 0.f, 0.f, 0.f);
    for (int j = i; j < NN * F1 / 4; j += stride) ((float4*)g_aggr1)[j] = z;
    for (int j = i; j < NN * F2 / 4; j += stride) ((float4*)g_aggr2)[j] = z;
    for (int j = i; j < NN * H1; j += stride) g_den1[j] = 0.f;
    for (int j = i; j < NN; j += stride)      { g_den2[j] = 0.f; g_cnt[j] = 0; }
}

// ---------------- counting sort by dst --------------------------------------
__global__ void hist_kernel(const int* __restrict__ ei, int E) {
    int i = blockIdx.x * blockDim.x + threadIdx.x;
    int stride = gridDim.x * blockDim.x;
    for (int e = i; e < E; e += stride)
        atomicAdd(&g_cnt[ei[E + e]], 1);
}

__global__ void scanA_kernel() {   // per-block sums of g_cnt
    __shared__ int sh[256];
    int b = blockIdx.x, t = threadIdx.x;
    int i = b * 256 + t;
    int v = (i < NN) ? g_cnt[i] : 0;
    sh[t] = v; __syncthreads();
    for (int off = 128; off; off >>= 1) {
        if (t < off) sh[t] += sh[t + off];
        __syncthreads();
    }
    if (t == 0) g_bsum[b] = sh[0];
}

__global__ void scanB_kernel() {   // exclusive scan of block sums (tiny)
    if (threadIdx.x == 0) {
        int run = 0;
        for (int b = 0; b < SCAN_B; b++) { int t = g_bsum[b]; g_bsum[b] = run; run += t; }
    }
}

__global__ void scanC_kernel() {   // per-block exclusive scan + offset -> g_pos
    __shared__ int sh[256];
    int b = blockIdx.x, t = threadIdx.x;
    int i = b * 256 + t;
    int v = (i < NN) ? g_cnt[i] : 0;
    sh[t] = v; __syncthreads();
#pragma unroll
    for (int off = 1; off < 256; off <<= 1) {
        int x = (t >= off) ? sh[t - off] : 0;
        __syncthreads();
        sh[t] += x;
        __syncthreads();
    }
    if (i < NN) g_pos[i] = g_bsum[b] + sh[t] - v;   // exclusive
}

__global__ void scatter_kernel(const int* __restrict__ ei, int E) {
    int i = blockIdx.x * blockDim.x + threadIdx.x;
    int stride = gridDim.x * blockDim.x;
    for (int e = i; e < E; e += stride) {
        int s = ei[e], d = ei[E + e];
        int pos = atomicAdd(&g_pos[d], 1);
        g_perm[pos] = make_int2(s, d);
    }
}

// ---------------- SGEMM: C[N,M] = A[N,K] @ B[K,M] ---------------------------
__global__ void sgemm64(const float* __restrict__ A, const float* __restrict__ B,
                        float* __restrict__ C, int N, int K, int M) {
    __shared__ float As[16][64];
    __shared__ float Bs[16][64];
    int tid = threadIdx.x;
    int tx = tid & 15, ty = tid >> 4;
    int rowBase = blockIdx.y * 64;
    int colBase = blockIdx.x * 64;

    int ar = tid >> 2;
    int ak = (tid & 3) * 4;
    int bk = tid >> 4;
    int bc = (tid & 15) * 4;

    float acc[4][4] = {};

    for (int k0 = 0; k0 < K; k0 += 16) {
        float4 av = make_float4(0.f, 0.f, 0.f, 0.f);
        int arow = rowBase + ar;
        if (arow < N)
            av = *(const float4*)(A + (size_t)arow * K + k0 + ak);
        As[ak + 0][ar] = av.x;
        As[ak + 1][ar] = av.y;
        As[ak + 2][ar] = av.z;
        As[ak + 3][ar] = av.w;

        float4 bv = *(const float4*)(B + (size_t)(k0 + bk) * M + colBase + bc);
        *(float4*)&Bs[bk][bc] = bv;
        __syncthreads();

#pragma unroll
        for (int k = 0; k < 16; k++) {
            float4 a4 = *(float4*)&As[k][ty * 4];
            float4 b4 = *(float4*)&Bs[k][tx * 4];
            float a[4] = {a4.x, a4.y, a4.z, a4.w};
            float b[4] = {b4.x, b4.y, b4.z, b4.w};
#pragma unroll
            for (int i = 0; i < 4; i++)
#pragma unroll
                for (int j = 0; j < 4; j++)
                    acc[i][j] += a[i] * b[j];
        }
        __syncthreads();
    }

#pragma unroll
    for (int i = 0; i < 4; i++) {
        int r = rowBase + ty * 4 + i;
        if (r < N) {
#pragma unroll
            for (int j = 0; j < 4; j++)
                C[(size_t)r * M + colBase + tx * 4 + j] = acc[i][j];
        }
    }
}

// ---------------- layer-1 edge pass over dst-sorted chunks ------------------
// One warp per chunk of PE1 edges. Register accumulators per dst-run.
__global__ void agg_edge1(const float* __restrict__ att, int E) {
    int warp = (int)((blockIdx.x * blockDim.x + threadIdx.x) >> 5);
    int lane = threadIdx.x & 31;
    int start = warp * PE1;
    if (start >= E) return;
    int end = min(E, start + PE1);

    const float4* pa = (const float4*)att;
    float4 t0 = pa[lane], t1 = pa[32 + lane];

    float4 b0, b1;
    float4 acc0 = make_float4(0, 0, 0, 0), acc1 = make_float4(0, 0, 0, 0);
    float dn0 = 0.f, dn1 = 0.f;
    int cur = -1;

    for (int e = start; e < end; e++) {
        int2 sd = g_perm[e];
        if (sd.y != cur) {
            if (cur >= 0) {  // flush
                float* dst = g_aggr1 + (size_t)cur * F1;
                red_add_v4(dst + 4 * lane, acc0);
                red_add_v4(dst + 4 * (32 + lane), acc1);
                if ((lane & 7) == 0) {
                    int g = lane >> 3;
                    red_add_f32(&g_den1[cur * H1 + g], dn0);
                    red_add_f32(&g_den1[cur * H1 + 4 + g], dn1);
                }
                acc0 = make_float4(0, 0, 0, 0); acc1 = make_float4(0, 0, 0, 0);
                dn0 = 0.f; dn1 = 0.f;
            }
            cur = sd.y;
            const float4* pr = (const float4*)(g_xr1 + (size_t)cur * F1);
            b0 = pr[lane]; b1 = pr[32 + lane];
        }
        const float4* pl = (const float4*)(g_xl1 + (size_t)sd.x * F1);
        float4 a0 = pl[lane], a1 = pl[32 + lane];

        float v, p0 = 0.f, p1 = 0.f;
        v = a0.x + b0.x; p0 += (v > 0.f ? v : 0.2f * v) * t0.x;
        v = a0.y + b0.y; p0 += (v > 0.f ? v : 0.2f * v) * t0.y;
        v = a0.z + b0.z; p0 += (v > 0.f ? v : 0.2f * v) * t0.z;
        v = a0.w + b0.w; p0 += (v > 0.f ? v : 0.2f * v) * t0.w;
        v = a1.x + b1.x; p1 += (v > 0.f ? v : 0.2f * v) * t1.x;
        v = a1.y + b1.y; p1 += (v > 0.f ? v : 0.2f * v) * t1.y;
        v = a1.z + b1.z; p1 += (v > 0.f ? v : 0.2f * v) * t1.z;
        v = a1.w + b1.w; p1 += (v > 0.f ? v : 0.2f * v) * t1.w;

#pragma unroll
        for (int o = 1; o < 8; o <<= 1) {
            p0 += __shfl_xor_sync(0xFFFFFFFFu, p0, o);
            p1 += __shfl_xor_sync(0xFFFFFFFFu, p1, o);
        }
        float e0 = __expf(p0);
        float e1 = __expf(p1);

        acc0.x += a0.x * e0; acc0.y += a0.y * e0; acc0.z += a0.z * e0; acc0.w += a0.w * e0;
        acc1.x += a1.x * e1; acc1.y += a1.y * e1; acc1.z += a1.z * e1; acc1.w += a1.w * e1;
        dn0 += e0; dn1 += e1;
    }
    // final flush
    if (cur >= 0) {
        float* dst = g_aggr1 + (size_t)cur * F1;
        red_add_v4(dst + 4 * lane, acc0);
        red_add_v4(dst + 4 * (32 + lane), acc1);
        if ((lane & 7) == 0) {
            int g = lane >> 3;
            red_add_f32(&g_den1[cur * H1 + g], dn0);
            red_add_f32(&g_den1[cur * H1 + 4 + g], dn1);
        }
    }
}

__global__ void finalize1(const float* __restrict__ b1) {
    int i = blockIdx.x * blockDim.x + threadIdx.x;   // float4 index
    if (i >= NN * F1 / 4) return;
    int n = i >> 6;
    int j4 = i & 63;
    int h = j4 >> 3;
    float inv = 1.f / (g_den1[n * H1 + h] + 1e-16f);
    float4 a = ((const float4*)g_aggr1)[i];
    float4 bb = ((const float4*)b1)[j4];
    float4 r;
    r.x = fmaxf(a.x * inv + bb.x, 0.f);
    r.y = fmaxf(a.y * inv + bb.y, 0.f);
    r.z = fmaxf(a.z * inv + bb.z, 0.f);
    r.w = fmaxf(a.w * inv + bb.w, 0.f);
    ((float4*)g_h1)[i] = r;
}

// ---------------- layer-2 edge pass (H=1, C=64), half-warp chunks -----------
__global__ void agg_edge2(const float* __restrict__ att, int E) {
    int hw = (int)((blockIdx.x * blockDim.x + threadIdx.x) >> 4);  // half-warp id
    int l16 = threadIdx.x & 15;
    unsigned hm = 0xFFFFu << (threadIdx.x & 16);   // mask of this half-warp
    int start = hw * PE2;
    if (start >= E) return;
    int end = min(E, start + PE2);

    float4 t = ((const float4*)att)[l16];
    float4 b;
    float4 acc = make_float4(0, 0, 0, 0);
    float dn = 0.f;
    int cur = -1;

    for (int e = start; e < end; e++) {
        int2 sd = g_perm[e];
        if (sd.y != cur) {
            if (cur >= 0) {
                red_add_v4(g_aggr2 + (size_t)cur * F2 + 4 * l16, acc);
                if (l16 == 0) red_add_f32(&g_den2[cur], dn);
                acc = make_float4(0, 0, 0, 0); dn = 0.f;
            }
            cur = sd.y;
            b = ((const float4*)(g_xr2 + (size_t)cur * F2))[l16];
        }
        float4 a = ((const float4*)(g_xl2 + (size_t)sd.x * F2))[l16];

        float v, p = 0.f;
        v = a.x + b.x; p += (v > 0.f ? v : 0.2f * v) * t.x;
        v = a.y + b.y; p += (v > 0.f ? v : 0.2f * v) * t.y;
        v = a.z + b.z; p += (v > 0.f ? v : 0.2f * v) * t.z;
        v = a.w + b.w; p += (v > 0.f ? v : 0.2f * v) * t.w;

#pragma unroll
        for (int o = 1; o < 16; o <<= 1) p += __shfl_xor_sync(hm, p, o);
        float ex = __expf(p);

        acc.x += a.x * ex; acc.y += a.y * ex; acc.z += a.z * ex; acc.w += a.w * ex;
        dn += ex;
    }
    if (cur >= 0) {
        red_add_v4(g_aggr2 + (size_t)cur * F2 + 4 * l16, acc);
        if (l16 == 0) red_add_f32(&g_den2[cur], dn);
    }
}

// one warp per node: bias add + log_softmax over 64
__global__ void finalize2(const float* __restrict__ b2, float* __restrict__ out) {
    int n = (int)((blockIdx.x * blockDim.x + threadIdx.x) >> 5);
    int lane = threadIdx.x & 31;
    if (n >= NN) return;
    float inv = 1.f / (g_den2[n] + 1e-16f);
    float v0 = g_aggr2[(size_t)n * F2 + lane]      * inv + b2[lane];
    float v1 = g_aggr2[(size_t)n * F2 + 32 + lane] * inv + b2[32 + lane];
    float mx = fmaxf(v0, v1);
#pragma unroll
    for (int o = 16; o; o >>= 1) mx = fmaxf(mx, __shfl_xor_sync(0xFFFFFFFFu, mx, o));
    float se = __expf(v0 - mx) + __expf(v1 - mx);
#pragma unroll
    for (int o = 16; o; o >>= 1) se += __shfl_xor_sync(0xFFFFFFFFu, se, o);
    float lse = mx + __logf(se);
    out[(size_t)n * F2 + lane]      = v0;
    out[(size_t)n * F2 + 32 + lane] = v1;
    out[(size_t)NN * F2 + (size_t)n * F2 + lane]      = v0 - lse;
    out[(size_t)NN * F2 + (size_t)n * F2 + 32 + lane] = v1 - lse;
}

// ---------------- launch ----------------------------------------------------
extern "C" void kernel_launch(void* const* d_in, const int* in_sizes, int n_in,
                              void* d_out, int out_size) {
    const float* x    = (const float*)d_in[0];
    const int*   ei   = (const int*)d_in[1];     // JAX canonicalizes int64 -> int32
    const float* Wl1  = (const float*)d_in[2];
    const float* Wr1  = (const float*)d_in[3];
    const float* att1 = (const float*)d_in[4];
    const float* b1   = (const float*)d_in[5];
    const float* Wl2  = (const float*)d_in[6];
    const float* Wr2  = (const float*)d_in[7];
    const float* att2 = (const float*)d_in[8];
    const float* b2   = (const float*)d_in[9];
    float* out = (float*)d_out;

    int E = in_sizes[1] / 2;
    if (E > EE) E = EE;
    int N = in_sizes[0] / F1;
    if (N > NN) N = NN;

    void *xl1p, *xr1p, *h1p, *xl2p, *xr2p;
    cudaGetSymbolAddress(&xl1p, g_xl1);
    cudaGetSymbolAddress(&xr1p, g_xr1);
    cudaGetSymbolAddress(&h1p,  g_h1);
    cudaGetSymbolAddress(&xl2p, g_xl2);
    cudaGetSymbolAddress(&xr2p, g_xr2);

    init_kernel<<<2048, 256>>>();

    // dst-sorted edge permutation (shared by both layers)
    hist_kernel<<<1024, 256>>>(ei, E);
    scanA_kernel<<<SCAN_B, 256>>>();
    scanB_kernel<<<1, 32>>>();
    scanC_kernel<<<SCAN_B, 256>>>();
    scatter_kernel<<<1024, 256>>>(ei, E);

    // layer 1 projections: [N,256] @ [256,256]
    dim3 grid1(F1 / 64, (N + 63) / 64);
    sgemm64<<<grid1, 256>>>(x, Wl1, (float*)xl1p, N, F1, F1);
    sgemm64<<<grid1, 256>>>(x, Wr1, (float*)xr1p, N, F1, F1);

    int chunks1 = (E + PE1 - 1) / PE1;              // warps
    agg_edge1<<<(chunks1 + 7) / 8, 256>>>(att1, E);
    finalize1<<<(NN * F1 / 4 + 255) / 256, 256>>>(b1);

    // layer 2 projections: [N,256] @ [256,64]
    dim3 grid2(F2 / 64, (N + 63) / 64);
    sgemm64<<<grid2, 256>>>((const float*)h1p, Wl2, (float*)xl2p, N, F1, F2);
    sgemm64<<<grid2, 256>>>((const float*)h1p, Wr2, (float*)xr2p, N, F1, F2);

    int chunks2 = (E + PE2 - 1) / PE2;              // half-warps
    agg_edge2<<<(chunks2 + 15) / 16, 256>>>(att2, E);
    finalize2<<<(NN * 32 + 255) / 256, 256>>>(b2, out);

    (void)n_in; (void)out_size;
}

// round 7
// speedup vs baseline: 3.6538x; 1.7278x over previous
#include <cuda_runtime.h>
#include <cstdint>

#define NN 50000
#define EE 800000
#define F1 256      // layer1 hidden (H*C = 8*32)
#define H1 8
#define F2 64       // layer2 output
#define PE1 16      // edges per warp chunk (layer1)
#define PE2 16      // edges per half-warp chunk (layer2)
#define SCAN_B 196  // ceil(50000/256)

// ---------------- static scratch ----------
__device__ float g_xlr1[(size_t)NN * 512];   // [n][0:256)=xl1, [256:512)=xr1
__device__ float g_aggr1[NN * F1];
__device__ float g_h1[NN * F1];
__device__ float g_den1[NN * H1];

__device__ float g_xlr2[(size_t)NN * 128];   // [n][0:64)=xl2, [64:128)=xr2
__device__ float g_aggr2[NN * F2];
__device__ float g_den2[NN];

__device__ float g_Bp1[256 * 512];           // Wl1 | Wr1
__device__ float g_Bp2[256 * 128];           // Wl2 | Wr2

// sort scratch
__device__ int  g_cnt[NN];
__device__ int  g_bsum[SCAN_B];
__device__ int  g_pos[NN];
__device__ int2 g_perm[EE];     // (src, dst) sorted by dst

__device__ __forceinline__ void red_add_v4(float* p, float4 v) {
    asm volatile("red.global.add.v4.f32 [%0], {%1,%2,%3,%4};"
                 :: "l"(p), "f"(v.x), "f"(v.y), "f"(v.z), "f"(v.w) : "memory");
}
__device__ __forceinline__ void red_add_f32(float* p, float v) {
    asm volatile("red.global.add.f32 [%0], %1;" :: "l"(p), "f"(v) : "memory");
}
__device__ __forceinline__ uint32_t to_tf32(float f) {
    uint32_t o;
    asm("cvt.rna.tf32.f32 %0, %1;" : "=r"(o) : "f"(f));
    return o;
}

// ---------------- init ------------------------------------------------------
__global__ void init_kernel() {
    int i = blockIdx.x * blockDim.x + threadIdx.x;
    int stride = gridDim.x * blockDim.x;
    float4 z = make_float4(0.f, 0.f, 0.f, 0.f);
    for (int j = i; j < NN * F1 / 4; j += stride) ((float4*)g_aggr1)[j] = z;
    for (int j = i; j < NN * F2 / 4; j += stride) ((float4*)g_aggr2)[j] = z;
    for (int j = i; j < NN * H1; j += stride) g_den1[j] = 0.f;
    for (int j = i; j < NN; j += stride)      { g_den2[j] = 0.f; g_cnt[j] = 0; }
}

// ---------------- weight packing: Bp = [Wl | Wr] ----------------------------
__global__ void pack_kernel(const float* __restrict__ Wl, const float* __restrict__ Wr,
                            float* __restrict__ Bp, int K, int Mh) {
    int i = blockIdx.x * blockDim.x + threadIdx.x;
    if (i >= K * Mh) return;
    int k = i / Mh, j = i % Mh;
    Bp[(size_t)k * 2 * Mh + j]      = Wl[i];
    Bp[(size_t)k * 2 * Mh + Mh + j] = Wr[i];
}

// ---------------- counting sort by dst --------------------------------------
__global__ void hist_kernel(const int* __restrict__ ei, int E) {
    int i = blockIdx.x * blockDim.x + threadIdx.x;
    int stride = gridDim.x * blockDim.x;
    for (int e = i; e < E; e += stride)
        atomicAdd(&g_cnt[ei[E + e]], 1);
}

__global__ void scanA_kernel() {
    __shared__ int sh[256];
    int b = blockIdx.x, t = threadIdx.x;
    int i = b * 256 + t;
    int v = (i < NN) ? g_cnt[i] : 0;
    sh[t] = v; __syncthreads();
    for (int off = 128; off; off >>= 1) {
        if (t < off) sh[t] += sh[t + off];
        __syncthreads();
    }
    if (t == 0) g_bsum[b] = sh[0];
}

__global__ void scanB_kernel() {
    if (threadIdx.x == 0) {
        int run = 0;
        for (int b = 0; b < SCAN_B; b++) { int t = g_bsum[b]; g_bsum[b] = run; run += t; }
    }
}

__global__ void scanC_kernel() {
    __shared__ int sh[256];
    int b = blockIdx.x, t = threadIdx.x;
    int i = b * 256 + t;
    int v = (i < NN) ? g_cnt[i] : 0;
    sh[t] = v; __syncthreads();
#pragma unroll
    for (int off = 1; off < 256; off <<= 1) {
        int x = (t >= off) ? sh[t - off] : 0;
        __syncthreads();
        sh[t] += x;
        __syncthreads();
    }
    if (i < NN) g_pos[i] = g_bsum[b] + sh[t] - v;
}

__global__ void scatter_kernel(const int* __restrict__ ei, int E) {
    int i = blockIdx.x * blockDim.x + threadIdx.x;
    int stride = gridDim.x * blockDim.x;
    for (int e = i; e < E; e += stride) {
        int s = ei[e], d = ei[E + e];
        int pos = atomicAdd(&g_pos[d], 1);
        g_perm[pos] = make_int2(s, d);
    }
}

// ---------------- TF32 tensor GEMM: C[N,M] = A[N,K] @ B[K,M] ----------------
// Block 128x128, BK=16, 8 warps (2 along M-rows x 4 along N-cols),
// warp tile 64x32 = 4x4 m16n8k8 tiles, fp32 accumulate.
__global__ __launch_bounds__(256) void tf32_gemm(
        const float* __restrict__ A, const float* __restrict__ B,
        float* __restrict__ C, int N, int K, int M) {
    __shared__ uint32_t As[128][18];     // [row][k] padded
    __shared__ uint32_t Bs[16][132];     // [k][col] padded

    int tid = threadIdx.x;
    int lane = tid & 31;
    int wid = tid >> 5;
    int wm = wid >> 2;           // 0..1
    int wn = wid & 3;            // 0..3
    int rowBase = blockIdx.y * 128;
    int colBase = blockIdx.x * 128;

    float c[16][4] = {};         // [mi*4+ni][reg]

    int l4 = lane >> 2;          // 0..7 groupID
    int l3 = lane & 3;           // 0..3

    for (int k0 = 0; k0 < K; k0 += 16) {
        // load A tile 128x16 (2 float4 per thread)
#pragma unroll
        for (int i = 0; i < 2; i++) {
            int r = (tid >> 2) + 64 * i;
            int kk = (tid & 3) * 4;
            int grow = rowBase + r;
            float4 v = make_float4(0.f, 0.f, 0.f, 0.f);
            if (grow < N) v = *(const float4*)(A + (size_t)grow * K + k0 + kk);
            As[r][kk + 0] = to_tf32(v.x);
            As[r][kk + 1] = to_tf32(v.y);
            As[r][kk + 2] = to_tf32(v.z);
            As[r][kk + 3] = to_tf32(v.w);
        }
        // load B tile 16x128 (2 float4 per thread)
#pragma unroll
        for (int i = 0; i < 2; i++) {
            int kk = (tid >> 5) + 8 * i;
            int cc = (tid & 31) * 4;
            float4 v = *(const float4*)(B + (size_t)(k0 + kk) * M + colBase + cc);
            Bs[kk][cc + 0] = to_tf32(v.x);
            Bs[kk][cc + 1] = to_tf32(v.y);
            Bs[kk][cc + 2] = to_tf32(v.z);
            Bs[kk][cc + 3] = to_tf32(v.w);
        }
        __syncthreads();

#pragma unroll
        for (int ks = 0; ks < 2; ks++) {
            int kb = ks * 8;
            uint32_t af[4][4];
#pragma unroll
            for (int mi = 0; mi < 4; mi++) {
                int r = wm * 64 + mi * 16 + l4;
                af[mi][0] = As[r][kb + l3];
                af[mi][1] = As[r + 8][kb + l3];
                af[mi][2] = As[r][kb + l3 + 4];
                af[mi][3] = As[r + 8][kb + l3 + 4];
            }
            uint32_t bf[4][2];
#pragma unroll
            for (int ni = 0; ni < 4; ni++) {
                int ccol = wn * 32 + ni * 8 + l4;
                bf[ni][0] = Bs[kb + l3][ccol];
                bf[ni][1] = Bs[kb + l3 + 4][ccol];
            }
#pragma unroll
            for (int mi = 0; mi < 4; mi++)
#pragma unroll
                for (int ni = 0; ni < 4; ni++) {
                    float* cr = c[mi * 4 + ni];
                    asm volatile(
                        "mma.sync.aligned.m16n8k8.row.col.f32.tf32.tf32.f32 "
                        "{%0,%1,%2,%3}, {%4,%5,%6,%7}, {%8,%9}, {%0,%1,%2,%3};"
                        : "+f"(cr[0]), "+f"(cr[1]), "+f"(cr[2]), "+f"(cr[3])
                        : "r"(af[mi][0]), "r"(af[mi][1]), "r"(af[mi][2]), "r"(af[mi][3]),
                          "r"(bf[ni][0]), "r"(bf[ni][1]));
                }
        }
        __syncthreads();
    }

    // store: c0,c1 -> (row, col..col+1), c2,c3 -> (row+8, ...)
#pragma unroll
    for (int mi = 0; mi < 4; mi++) {
        int r0 = rowBase + wm * 64 + mi * 16 + l4;
#pragma unroll
        for (int ni = 0; ni < 4; ni++) {
            int cc = colBase + wn * 32 + ni * 8 + l3 * 2;
            float* cr = c[mi * 4 + ni];
            if (r0 < N)
                *(float2*)(C + (size_t)r0 * M + cc) = make_float2(cr[0], cr[1]);
            if (r0 + 8 < N)
                *(float2*)(C + (size_t)(r0 + 8) * M + cc) = make_float2(cr[2], cr[3]);
        }
    }
}

// ---------------- layer-1 edge pass over dst-sorted chunks ------------------
__global__ void agg_edge1(const float* __restrict__ att, int E) {
    int warp = (int)((blockIdx.x * blockDim.x + threadIdx.x) >> 5);
    int lane = threadIdx.x & 31;
    int start = warp * PE1;
    if (start >= E) return;
    int end = min(E, start + PE1);

    const float4* pa = (const float4*)att;
    float4 t0 = pa[lane], t1 = pa[32 + lane];

    float4 b0, b1;
    float4 acc0 = make_float4(0, 0, 0, 0), acc1 = make_float4(0, 0, 0, 0);
    float dn0 = 0.f, dn1 = 0.f;
    int cur = -1;

    for (int e = start; e < end; e++) {
        int2 sd = g_perm[e];
        if (sd.y != cur) {
            if (cur >= 0) {
                float* dst = g_aggr1 + (size_t)cur * F1;
                red_add_v4(dst + 4 * lane, acc0);
                red_add_v4(dst + 4 * (32 + lane), acc1);
                if ((lane & 7) == 0) {
                    int g = lane >> 3;
                    red_add_f32(&g_den1[cur * H1 + g], dn0);
                    red_add_f32(&g_den1[cur * H1 + 4 + g], dn1);
                }
                acc0 = make_float4(0, 0, 0, 0); acc1 = make_float4(0, 0, 0, 0);
                dn0 = 0.f; dn1 = 0.f;
            }
            cur = sd.y;
            const float4* pr = (const float4*)(g_xlr1 + (size_t)cur * 512 + 256);
            b0 = pr[lane]; b1 = pr[32 + lane];
        }
        const float4* pl = (const float4*)(g_xlr1 + (size_t)sd.x * 512);
        float4 a0 = pl[lane], a1 = pl[32 + lane];

        float v, p0 = 0.f, p1 = 0.f;
        v = a0.x + b0.x; p0 += (v > 0.f ? v : 0.2f * v) * t0.x;
        v = a0.y + b0.y; p0 += (v > 0.f ? v : 0.2f * v) * t0.y;
        v = a0.z + b0.z; p0 += (v > 0.f ? v : 0.2f * v) * t0.z;
        v = a0.w + b0.w; p0 += (v > 0.f ? v : 0.2f * v) * t0.w;
        v = a1.x + b1.x; p1 += (v > 0.f ? v : 0.2f * v) * t1.x;
        v = a1.y + b1.y; p1 += (v > 0.f ? v : 0.2f * v) * t1.y;
        v = a1.z + b1.z; p1 += (v > 0.f ? v : 0.2f * v) * t1.z;
        v = a1.w + b1.w; p1 += (v > 0.f ? v : 0.2f * v) * t1.w;

#pragma unroll
        for (int o = 1; o < 8; o <<= 1) {
            p0 += __shfl_xor_sync(0xFFFFFFFFu, p0, o);
            p1 += __shfl_xor_sync(0xFFFFFFFFu, p1, o);
        }
        float e0 = __expf(p0);
        float e1 = __expf(p1);

        acc0.x += a0.x * e0; acc0.y += a0.y * e0; acc0.z += a0.z * e0; acc0.w += a0.w * e0;
        acc1.x += a1.x * e1; acc1.y += a1.y * e1; acc1.z += a1.z * e1; acc1.w += a1.w * e1;
        dn0 += e0; dn1 += e1;
    }
    if (cur >= 0) {
        float* dst = g_aggr1 + (size_t)cur * F1;
        red_add_v4(dst + 4 * lane, acc0);
        red_add_v4(dst + 4 * (32 + lane), acc1);
        if ((lane & 7) == 0) {
            int g = lane >> 3;
            red_add_f32(&g_den1[cur * H1 + g], dn0);
            red_add_f32(&g_den1[cur * H1 + 4 + g], dn1);
        }
    }
}

__global__ void finalize1(const float* __restrict__ b1) {
    int i = blockIdx.x * blockDim.x + threadIdx.x;   // float4 index
    if (i >= NN * F1 / 4) return;
    int n = i >> 6;
    int j4 = i & 63;
    int h = j4 >> 3;
    float inv = 1.f / (g_den1[n * H1 + h] + 1e-16f);
    float4 a = ((const float4*)g_aggr1)[i];
    float4 bb = ((const float4*)b1)[j4];
    float4 r;
    r.x = fmaxf(a.x * inv + bb.x, 0.f);
    r.y = fmaxf(a.y * inv + bb.y, 0.f);
    r.z = fmaxf(a.z * inv + bb.z, 0.f);
    r.w = fmaxf(a.w * inv + bb.w, 0.f);
    ((float4*)g_h1)[i] = r;
}

// ---------------- layer-2 edge pass (H=1, C=64), half-warp chunks -----------
__global__ void agg_edge2(const float* __restrict__ att, int E) {
    int hw = (int)((blockIdx.x * blockDim.x + threadIdx.x) >> 4);
    int l16 = threadIdx.x & 15;
    unsigned hm = 0xFFFFu << (threadIdx.x & 16);
    int start = hw * PE2;
    if (start >= E) return;
    int end = min(E, start + PE2);

    float4 t = ((const float4*)att)[l16];
    float4 b;
    float4 acc = make_float4(0, 0, 0, 0);
    float dn = 0.f;
    int cur = -1;

    for (int e = start; e < end; e++) {
        int2 sd = g_perm[e];
        if (sd.y != cur) {
            if (cur >= 0) {
                red_add_v4(g_aggr2 + (size_t)cur * F2 + 4 * l16, acc);
                if (l16 == 0) red_add_f32(&g_den2[cur], dn);
                acc = make_float4(0, 0, 0, 0); dn = 0.f;
            }
            cur = sd.y;
            b = ((const float4*)(g_xlr2 + (size_t)cur * 128 + 64))[l16];
        }
        float4 a = ((const float4*)(g_xlr2 + (size_t)sd.x * 128))[l16];

        float v, p = 0.f;
        v = a.x + b.x; p += (v > 0.f ? v : 0.2f * v) * t.x;
        v = a.y + b.y; p += (v > 0.f ? v : 0.2f * v) * t.y;
        v = a.z + b.z; p += (v > 0.f ? v : 0.2f * v) * t.z;
        v = a.w + b.w; p += (v > 0.f ? v : 0.2f * v) * t.w;

#pragma unroll
        for (int o = 1; o < 16; o <<= 1) p += __shfl_xor_sync(hm, p, o);
        float ex = __expf(p);

        acc.x += a.x * ex; acc.y += a.y * ex; acc.z += a.z * ex; acc.w += a.w * ex;
        dn += ex;
    }
    if (cur >= 0) {
        red_add_v4(g_aggr2 + (size_t)cur * F2 + 4 * l16, acc);
        if (l16 == 0) red_add_f32(&g_den2[cur], dn);
    }
}

// one warp per node: bias add + log_softmax over 64
__global__ void finalize2(const float* __restrict__ b2, float* __restrict__ out) {
    int n = (int)((blockIdx.x * blockDim.x + threadIdx.x) >> 5);
    int lane = threadIdx.x & 31;
    if (n >= NN) return;
    float inv = 1.f / (g_den2[n] + 1e-16f);
    float v0 = g_aggr2[(size_t)n * F2 + lane]      * inv + b2[lane];
    float v1 = g_aggr2[(size_t)n * F2 + 32 + lane] * inv + b2[32 + lane];
    float mx = fmaxf(v0, v1);
#pragma unroll
    for (int o = 16; o; o >>= 1) mx = fmaxf(mx, __shfl_xor_sync(0xFFFFFFFFu, mx, o));
    float se = __expf(v0 - mx) + __expf(v1 - mx);
#pragma unroll
    for (int o = 16; o; o >>= 1) se += __shfl_xor_sync(0xFFFFFFFFu, se, o);
    float lse = mx + __logf(se);
    out[(size_t)n * F2 + lane]      = v0;
    out[(size_t)n * F2 + 32 + lane] = v1;
    out[(size_t)NN * F2 + (size_t)n * F2 + lane]      = v0 - lse;
    out[(size_t)NN * F2 + (size_t)n * F2 + 32 + lane] = v1 - lse;
}

// ---------------- launch ----------------------------------------------------
extern "C" void kernel_launch(void* const* d_in, const int* in_sizes, int n_in,
                              void* d_out, int out_size) {
    const float* x    = (const float*)d_in[0];
    const int*   ei   = (const int*)d_in[1];     // JAX canonicalizes int64 -> int32
    const float* Wl1  = (const float*)d_in[2];
    const float* Wr1  = (const float*)d_in[3];
    const float* att1 = (const float*)d_in[4];
    const float* b1   = (const float*)d_in[5];
    const float* Wl2  = (const float*)d_in[6];
    const float* Wr2  = (const float*)d_in[7];
    const float* att2 = (const float*)d_in[8];
    const float* b2   = (const float*)d_in[9];
    float* out = (float*)d_out;

    int E = in_sizes[1] / 2;
    if (E > EE) E = EE;
    int N = in_sizes[0] / F1;
    if (N > NN) N = NN;

    void *xlr1p, *xlr2p, *h1p, *bp1p, *bp2p;
    cudaGetSymbolAddress(&xlr1p, g_xlr1);
    cudaGetSymbolAddress(&xlr2p, g_xlr2);
    cudaGetSymbolAddress(&h1p,  g_h1);
    cudaGetSymbolAddress(&bp1p, g_Bp1);
    cudaGetSymbolAddress(&bp2p, g_Bp2);

    init_kernel<<<2048, 256>>>();

    // pack weights: Bp1 = [Wl1 | Wr1]  (256x512), Bp2 = [Wl2 | Wr2] (256x128)
    pack_kernel<<<(256 * 256 + 255) / 256, 256>>>(Wl1, Wr1, (float*)bp1p, 256, 256);
    pack_kernel<<<(256 * 64 + 255) / 256, 256>>>(Wl2, Wr2, (float*)bp2p, 256, 64);

    // dst-sorted edge permutation (shared by both layers)
    hist_kernel<<<1024, 256>>>(ei, E);
    scanA_kernel<<<SCAN_B, 256>>>();
    scanB_kernel<<<1, 32>>>();
    scanC_kernel<<<SCAN_B, 256>>>();
    scatter_kernel<<<1024, 256>>>(ei, E);

    // layer 1 projection: [N,256] @ [256,512] -> xlr1
    dim3 grid1(512 / 128, (N + 127) / 128);
    tf32_gemm<<<grid1, 256>>>(x, (const float*)bp1p, (float*)xlr1p, N, F1, 512);

    int chunks1 = (E + PE1 - 1) / PE1;
    agg_edge1<<<(chunks1 + 7) / 8, 256>>>(att1, E);
    finalize1<<<(NN * F1 / 4 + 255) / 256, 256>>>(b1);

    // layer 2 projection: [N,256] @ [256,128] -> xlr2
    dim3 grid2(1, (N + 127) / 128);
    tf32_gemm<<<grid2, 256>>>((const float*)h1p, (const float*)bp2p, (float*)xlr2p, N, F1, 128);

    int chunks2 = (E + PE2 - 1) / PE2;
    agg_edge2<<<(chunks2 + 15) / 16, 256>>>(att2, E);
    finalize2<<<(NN * 32 + 255) / 256, 256>>>(b2, out);

    (void)n_in; (void)out_size;
}

// round 10
// speedup vs baseline: 3.7533x; 1.0272x over previous
#include <cuda_runtime.h>
#include <cstdint>

#define NN 50000
#define EE 800000
#define F1 256      // layer1 hidden (H*C = 8*32)
#define H1 8
#define F2 64       // layer2 output
#define PE1 16      // edges per warp chunk (layer1)
#define PE2 16      // edges per half-warp chunk (layer2)
#define SCAN_B 196  // ceil(50000/256)

// ---------------- static scratch ----------
__device__ float g_xlr1[(size_t)NN * 512];   // [n][0:256)=xl1, [256:512)=xr1
__device__ float g_aggr1[NN * F1];
__device__ float g_den1[NN * H1];

__device__ float g_xlr2[(size_t)NN * 128];   // [n][0:64)=xl2, [64:128)=xr2
__device__ float g_aggr2[NN * F2];
__device__ float g_den2[NN];

__device__ float g_Bp1[256 * 512];           // Wl1 | Wr1
__device__ float g_Bp2[256 * 128];           // Wl2 | Wr2

// sort scratch
__device__ int  g_cnt[NN];
__device__ int  g_bsum[SCAN_B];
__device__ int  g_pos[NN];
__device__ int2 g_perm[EE];     // (src, dst) sorted by dst

__device__ __forceinline__ void red_add_v4(float* p, float4 v) {
    asm volatile("red.global.add.v4.f32 [%0], {%1,%2,%3,%4};"
                 :: "l"(p), "f"(v.x), "f"(v.y), "f"(v.z), "f"(v.w) : "memory");
}
__device__ __forceinline__ void red_add_f32(float* p, float v) {
    asm volatile("red.global.add.f32 [%0], %1;" :: "l"(p), "f"(v) : "memory");
}
__device__ __forceinline__ uint32_t to_tf32(float f) {
    uint32_t o;
    asm("cvt.rna.tf32.f32 %0, %1;" : "=r"(o) : "f"(f));
    return o;
}

// ---------------- init ------------------------------------------------------
__global__ void init_kernel() {
    int i = blockIdx.x * blockDim.x + threadIdx.x;
    int stride = gridDim.x * blockDim.x;
    float4 z = make_float4(0.f, 0.f, 0.f, 0.f);
    for (int j = i; j < NN * F1 / 4; j += stride) ((float4*)g_aggr1)[j] = z;
    for (int j = i; j < NN * F2 / 4; j += stride) ((float4*)g_aggr2)[j] = z;
    for (int j = i; j < NN * H1; j += stride) g_den1[j] = 0.f;
    for (int j = i; j < NN; j += stride)      { g_den2[j] = 0.f; g_cnt[j] = 0; }
}

// ---------------- weight packing: Bp = [Wl | Wr] ----------------------------
__global__ void pack_kernel(const float* __restrict__ Wl, const float* __restrict__ Wr,
                            float* __restrict__ Bp, int K, int Mh) {
    int i = blockIdx.x * blockDim.x + threadIdx.x;
    if (i >= K * Mh) return;
    int k = i / Mh, j = i % Mh;
    Bp[(size_t)k * 2 * Mh + j]      = Wl[i];
    Bp[(size_t)k * 2 * Mh + Mh + j] = Wr[i];
}

// ---------------- counting sort by dst --------------------------------------
__global__ void hist_kernel(const int* __restrict__ ei, int E) {
    int i = blockIdx.x * blockDim.x + threadIdx.x;
    int stride = gridDim.x * blockDim.x;
    for (int e = i; e < E; e += stride)
        atomicAdd(&g_cnt[ei[E + e]], 1);
}

__global__ void scanA_kernel() {
    __shared__ int sh[256];
    int b = blockIdx.x, t = threadIdx.x;
    int i = b * 256 + t;
    int v = (i < NN) ? g_cnt[i] : 0;
    sh[t] = v; __syncthreads();
    for (int off = 128; off; off >>= 1) {
        if (t < off) sh[t] += sh[t + off];
        __syncthreads();
    }
    if (t == 0) g_bsum[b] = sh[0];
}

__global__ void scanB_kernel() {    // exclusive scan of 196 block sums, 1 block
    __shared__ int sh[256];
    int t = threadIdx.x;
    int v = (t < SCAN_B) ? g_bsum[t] : 0;
    sh[t] = v; __syncthreads();
#pragma unroll
    for (int off = 1; off < 256; off <<= 1) {
        int x = (t >= off) ? sh[t - off] : 0;
        __syncthreads();
        sh[t] += x;
        __syncthreads();
    }
    if (t < SCAN_B) g_bsum[t] = sh[t] - v;   // exclusive
}

__global__ void scanC_kernel() {
    __shared__ int sh[256];
    int b = blockIdx.x, t = threadIdx.x;
    int i = b * 256 + t;
    int v = (i < NN) ? g_cnt[i] : 0;
    sh[t] = v; __syncthreads();
#pragma unroll
    for (int off = 1; off < 256; off <<= 1) {
        int x = (t >= off) ? sh[t - off] : 0;
        __syncthreads();
        sh[t] += x;
        __syncthreads();
    }
    if (i < NN) g_pos[i] = g_bsum[b] + sh[t] - v;
}

__global__ void scatter_kernel(const int* __restrict__ ei, int E) {
    int i = blockIdx.x * blockDim.x + threadIdx.x;
    int stride = gridDim.x * blockDim.x;
    for (int e = i; e < E; e += stride) {
        int s = ei[e], d = ei[E + e];
        int pos = atomicAdd(&g_pos[d], 1);
        g_perm[pos] = make_int2(s, d);
    }
}

// ---------------- TF32 tensor GEMM: C[N,M] = A[N,K] @ B[K,M] ----------------
// Block 128x128, BK=16, 8 warps (2x4), warp tile 64x32, fp32 accumulate.
// FUSED=1: A element = relu(aggr1[row][k]/den1[row][k>>5] + b1[k]) (layer-2 path).
template <int FUSED>
__global__ __launch_bounds__(256) void tf32_gemm(
        const float* __restrict__ A, const float* __restrict__ B,
        float* __restrict__ C, int N, int K, int M,
        const float* __restrict__ bias) {
    __shared__ uint32_t As[128][18];     // [row][k] padded
    __shared__ uint32_t Bs[16][132];     // [k][col] padded

    int tid = threadIdx.x;
    int lane = tid & 31;
    int wid = tid >> 5;
    int wm = wid >> 2;           // 0..1
    int wn = wid & 3;            // 0..3
    int rowBase = blockIdx.y * 128;
    int colBase = blockIdx.x * 128;

    float c[16][4] = {};

    int l4 = lane >> 2;          // 0..7
    int l3 = lane & 3;           // 0..3

    for (int k0 = 0; k0 < K; k0 += 16) {
#pragma unroll
        for (int i = 0; i < 2; i++) {
            int r = (tid >> 2) + 64 * i;
            int kk = (tid & 3) * 4;
            int grow = rowBase + r;
            float4 v = make_float4(0.f, 0.f, 0.f, 0.f);
            if (grow < N) {
                v = *(const float4*)(A + (size_t)grow * K + k0 + kk);
                if (FUSED) {
                    int kc = k0 + kk;
                    float inv = 1.f / (g_den1[grow * H1 + (kc >> 5)] + 1e-16f);
                    float4 bb = *(const float4*)(bias + kc);
                    v.x = fmaxf(v.x * inv + bb.x, 0.f);
                    v.y = fmaxf(v.y * inv + bb.y, 0.f);
                    v.z = fmaxf(v.z * inv + bb.z, 0.f);
                    v.w = fmaxf(v.w * inv + bb.w, 0.f);
                }
            }
            As[r][kk + 0] = to_tf32(v.x);
            As[r][kk + 1] = to_tf32(v.y);
            As[r][kk + 2] = to_tf32(v.z);
            As[r][kk + 3] = to_tf32(v.w);
        }
#pragma unroll
        for (int i = 0; i < 2; i++) {
            int kk = (tid >> 5) + 8 * i;
            int cc = (tid & 31) * 4;
            float4 v = *(const float4*)(B + (size_t)(k0 + kk) * M + colBase + cc);
            Bs[kk][cc + 0] = to_tf32(v.x);
            Bs[kk][cc + 1] = to_tf32(v.y);
            Bs[kk][cc + 2] = to_tf32(v.z);
            Bs[kk][cc + 3] = to_tf32(v.w);
        }
        __syncthreads();

#pragma unroll
        for (int ks = 0; ks < 2; ks++) {
            int kb = ks * 8;
            uint32_t af[4][4];
#pragma unroll
            for (int mi = 0; mi < 4; mi++) {
                int r = wm * 64 + mi * 16 + l4;
                af[mi][0] = As[r][kb + l3];
                af[mi][1] = As[r + 8][kb + l3];
                af[mi][2] = As[r][kb + l3 + 4];
                af[mi][3] = As[r + 8][kb + l3 + 4];
            }
            uint32_t bf[4][2];
#pragma unroll
            for (int ni = 0; ni < 4; ni++) {
                int ccol = wn * 32 + ni * 8 + l4;
                bf[ni][0] = Bs[kb + l3][ccol];
                bf[ni][1] = Bs[kb + l3 + 4][ccol];
            }
#pragma unroll
            for (int mi = 0; mi < 4; mi++)
#pragma unroll
                for (int ni = 0; ni < 4; ni++) {
                    float* cr = c[mi * 4 + ni];
                    asm volatile(
                        "mma.sync.aligned.m16n8k8.row.col.f32.tf32.tf32.f32 "
                        "{%0,%1,%2,%3}, {%4,%5,%6,%7}, {%8,%9}, {%0,%1,%2,%3};"
                        : "+f"(cr[0]), "+f"(cr[1]), "+f"(cr[2]), "+f"(cr[3])
                        : "r"(af[mi][0]), "r"(af[mi][1]), "r"(af[mi][2]), "r"(af[mi][3]),
                          "r"(bf[ni][0]), "r"(bf[ni][1]));
                }
        }
        __syncthreads();
    }

#pragma unroll
    for (int mi = 0; mi < 4; mi++) {
        int r0 = rowBase + wm * 64 + mi * 16 + l4;
#pragma unroll
        for (int ni = 0; ni < 4; ni++) {
            int cc = colBase + wn * 32 + ni * 8 + l3 * 2;
            float* cr = c[mi * 4 + ni];
            if (r0 < N)
                *(float2*)(C + (size_t)r0 * M + cc) = make_float2(cr[0], cr[1]);
            if (r0 + 8 < N)
                *(float2*)(C + (size_t)(r0 + 8) * M + cc) = make_float2(cr[2], cr[3]);
        }
    }
}

// ---------------- layer-1 edge pass over dst-sorted chunks ------------------
__global__ void agg_edge1(const float* __restrict__ att, int E) {
    int warp = (int)((blockIdx.x * blockDim.x + threadIdx.x) >> 5);
    int lane = threadIdx.x & 31;
    int start = warp * PE1;
    if (start >= E) return;
    int end = min(E, start + PE1);

    const float4* pa = (const float4*)att;
    float4 t0 = pa[lane], t1 = pa[32 + lane];

    float4 b0, b1;
    float4 acc0 = make_float4(0, 0, 0, 0), acc1 = make_float4(0, 0, 0, 0);
    float dn0 = 0.f, dn1 = 0.f;
    int cur = -1;

    for (int e = start; e < end; e++) {
        int2 sd = g_perm[e];
        if (sd.y != cur) {
            if (cur >= 0) {
                float* dst = g_aggr1 + (size_t)cur * F1;
                red_add_v4(dst + 4 * lane, acc0);
                red_add_v4(dst + 4 * (32 + lane), acc1);
                if ((lane & 7) == 0) {
                    int g = lane >> 3;
                    red_add_f32(&g_den1[cur * H1 + g], dn0);
                    red_add_f32(&g_den1[cur * H1 + 4 + g], dn1);
                }
                acc0 = make_float4(0, 0, 0, 0); acc1 = make_float4(0, 0, 0, 0);
                dn0 = 0.f; dn1 = 0.f;
            }
            cur = sd.y;
            const float4* pr = (const float4*)(g_xlr1 + (size_t)cur * 512 + 256);
            b0 = pr[lane]; b1 = pr[32 + lane];
        }
        const float4* pl = (const float4*)(g_xlr1 + (size_t)sd.x * 512);
        float4 a0 = pl[lane], a1 = pl[32 + lane];

        float v, p0 = 0.f, p1 = 0.f;
        v = a0.x + b0.x; p0 += (v > 0.f ? v : 0.2f * v) * t0.x;
        v = a0.y + b0.y; p0 += (v > 0.f ? v : 0.2f * v) * t0.y;
        v = a0.z + b0.z; p0 += (v > 0.f ? v : 0.2f * v) * t0.z;
        v = a0.w + b0.w; p0 += (v > 0.f ? v : 0.2f * v) * t0.w;
        v = a1.x + b1.x; p1 += (v > 0.f ? v : 0.2f * v) * t1.x;
        v = a1.y + b1.y; p1 += (v > 0.f ? v : 0.2f * v) * t1.y;
        v = a1.z + b1.z; p1 += (v > 0.f ? v : 0.2f * v) * t1.z;
        v = a1.w + b1.w; p1 += (v > 0.f ? v : 0.2f * v) * t1.w;

#pragma unroll
        for (int o = 1; o < 8; o <<= 1) {
            p0 += __shfl_xor_sync(0xFFFFFFFFu, p0, o);
            p1 += __shfl_xor_sync(0xFFFFFFFFu, p1, o);
        }
        float e0 = __expf(p0);
        float e1 = __expf(p1);

        acc0.x += a0.x * e0; acc0.y += a0.y * e0; acc0.z += a0.z * e0; acc0.w += a0.w * e0;
        acc1.x += a1.x * e1; acc1.y += a1.y * e1; acc1.z += a1.z * e1; acc1.w += a1.w * e1;
        dn0 += e0; dn1 += e1;
    }
    if (cur >= 0) {
        float* dst = g_aggr1 + (size_t)cur * F1;
        red_add_v4(dst + 4 * lane, acc0);
        red_add_v4(dst + 4 * (32 + lane), acc1);
        if ((lane & 7) == 0) {
            int g = lane >> 3;
            red_add_f32(&g_den1[cur * H1 + g], dn0);
            red_add_f32(&g_den1[cur * H1 + 4 + g], dn1);
        }
    }
}

// ---------------- layer-2 edge pass (H=1, C=64), half-warp chunks -----------
__global__ void agg_edge2(const float* __restrict__ att, int E) {
    int hw = (int)((blockIdx.x * blockDim.x + threadIdx.x) >> 4);
    int l16 = threadIdx.x & 15;
    unsigned hm = 0xFFFFu << (threadIdx.x & 16);
    int start = hw * PE2;
    if (start >= E) return;
    int end = min(E, start + PE2);

    float4 t = ((const float4*)att)[l16];
    float4 b;
    float4 acc = make_float4(0, 0, 0, 0);
    float dn = 0.f;
    int cur = -1;

    for (int e = start; e < end; e++) {
        int2 sd = g_perm[e];
        if (sd.y != cur) {
            if (cur >= 0) {
                red_add_v4(g_aggr2 + (size_t)cur * F2 + 4 * l16, acc);
                if (l16 == 0) red_add_f32(&g_den2[cur], dn);
                acc = make_float4(0, 0, 0, 0); dn = 0.f;
            }
            cur = sd.y;
            b = ((const float4*)(g_xlr2 + (size_t)cur * 128 + 64))[l16];
        }
        float4 a = ((const float4*)(g_xlr2 + (size_t)sd.x * 128))[l16];

        float v, p = 0.f;
        v = a.x + b.x; p += (v > 0.f ? v : 0.2f * v) * t.x;
        v = a.y + b.y; p += (v > 0.f ? v : 0.2f * v) * t.y;
        v = a.z + b.z; p += (v > 0.f ? v : 0.2f * v) * t.z;
        v = a.w + b.w; p += (v > 0.f ? v : 0.2f * v) * t.w;

#pragma unroll
        for (int o = 1; o < 16; o <<= 1) p += __shfl_xor_sync(hm, p, o);
        float ex = __expf(p);

        acc.x += a.x * ex; acc.y += a.y * ex; acc.z += a.z * ex; acc.w += a.w * ex;
        dn += ex;
    }
    if (cur >= 0) {
        red_add_v4(g_aggr2 + (size_t)cur * F2 + 4 * l16, acc);
        if (l16 == 0) red_add_f32(&g_den2[cur], dn);
    }
}

// one warp per node: bias add + log_softmax over 64
__global__ void finalize2(const float* __restrict__ b2, float* __restrict__ out) {
    int n = (int)((blockIdx.x * blockDim.x + threadIdx.x) >> 5);
    int lane = threadIdx.x & 31;
    if (n >= NN) return;
    float inv = 1.f / (g_den2[n] + 1e-16f);
    float v0 = g_aggr2[(size_t)n * F2 + lane]      * inv + b2[lane];
    float v1 = g_aggr2[(size_t)n * F2 + 32 + lane] * inv + b2[32 + lane];
    float mx = fmaxf(v0, v1);
#pragma unroll
    for (int o = 16; o; o >>= 1) mx = fmaxf(mx, __shfl_xor_sync(0xFFFFFFFFu, mx, o));
    float se = __expf(v0 - mx) + __expf(v1 - mx);
#pragma unroll
    for (int o = 16; o; o >>= 1) se += __shfl_xor_sync(0xFFFFFFFFu, se, o);
    float lse = mx + __logf(se);
    out[(size_t)n * F2 + lane]      = v0;
    out[(size_t)n * F2 + 32 + lane] = v1;
    out[(size_t)NN * F2 + (size_t)n * F2 + lane]      = v0 - lse;
    out[(size_t)NN * F2 + (size_t)n * F2 + 32 + lane] = v1 - lse;
}

// ---------------- launch ----------------------------------------------------
extern "C" void kernel_launch(void* const* d_in, const int* in_sizes, int n_in,
                              void* d_out, int out_size) {
    const float* x    = (const float*)d_in[0];
    const int*   ei   = (const int*)d_in[1];     // JAX canonicalizes int64 -> int32
    const float* Wl1  = (const float*)d_in[2];
    const float* Wr1  = (const float*)d_in[3];
    const float* att1 = (const float*)d_in[4];
    const float* b1   = (const float*)d_in[5];
    const float* Wl2  = (const float*)d_in[6];
    const float* Wr2  = (const float*)d_in[7];
    const float* att2 = (const float*)d_in[8];
    const float* b2   = (const float*)d_in[9];
    float* out = (float*)d_out;

    int E = in_sizes[1] / 2;
    if (E > EE) E = EE;
    int N = in_sizes[0] / F1;
    if (N > NN) N = NN;

    void *xlr1p, *xlr2p, *aggr1p, *bp1p, *bp2p;
    cudaGetSymbolAddress(&xlr1p, g_xlr1);
    cudaGetSymbolAddress(&xlr2p, g_xlr2);
    cudaGetSymbolAddress(&aggr1p, g_aggr1);
    cudaGetSymbolAddress(&bp1p, g_Bp1);
    cudaGetSymbolAddress(&bp2p, g_Bp2);

    // side streams + events, created lazily on the (uncaptured) correctness
    // call, reused inside graph capture via the event fork/join pattern.
    static cudaStream_t sA = nullptr, sB = nullptr;
    static cudaEvent_t ev0 = nullptr, evS = nullptr, evG = nullptr;
    if (!sA) {
        cudaStreamCreateWithFlags(&sA, cudaStreamNonBlocking);
        cudaStreamCreateWithFlags(&sB, cudaStreamNonBlocking);
        cudaEventCreateWithFlags(&ev0, cudaEventDisableTiming);
        cudaEventCreateWithFlags(&evS, cudaEventDisableTiming);
        cudaEventCreateWithFlags(&evG, cudaEventDisableTiming);
    }

    // fork
    cudaEventRecord(ev0, 0);
    cudaStreamWaitEvent(sA, ev0, 0);
    cudaStreamWaitEvent(sB, ev0, 0);

    // stream A: zero-init + dst-sorted edge permutation
    init_kernel<<<2048, 256, 0, sA>>>();
    hist_kernel<<<1024, 256, 0, sA>>>(ei, E);
    scanA_kernel<<<SCAN_B, 256, 0, sA>>>();
    scanB_kernel<<<1, 256, 0, sA>>>();
    scanC_kernel<<<SCAN_B, 256, 0, sA>>>();
    scatter_kernel<<<1024, 256, 0, sA>>>(ei, E);
    cudaEventRecord(evS, sA);

    // stream B: weight packing + layer-1 projection [N,256]@[256,512]
    pack_kernel<<<(256 * 256 + 255) / 256, 256, 0, sB>>>(Wl1, Wr1, (float*)bp1p, 256, 256);
    pack_kernel<<<(256 * 64 + 255) / 256, 256, 0, sB>>>(Wl2, Wr2, (float*)bp2p, 256, 64);
    dim3 grid1(512 / 128, (N + 127) / 128);
    tf32_gemm<0><<<grid1, 256, 0, sB>>>(x, (const float*)bp1p, (float*)xlr1p, N, F1, 512, nullptr);
    cudaEventRecord(evG, sB);

    // join on main stream
    cudaStreamWaitEvent(0, evS, 0);
    cudaStreamWaitEvent(0, evG, 0);

    int chunks1 = (E + PE1 - 1) / PE1;
    agg_edge1<<<(chunks1 + 7) / 8, 256>>>(att1, E);

    // layer 2 projection with fused finalize1 on the A-load path:
    // A = relu(aggr1/den1 + b1), [N,256]@[256,128] -> xlr2
    dim3 grid2(1, (N + 127) / 128);
    tf32_gemm<1><<<grid2, 256>>>((const float*)aggr1p, (const float*)bp2p,
                                 (float*)xlr2p, N, F1, 128, b1);

    int chunks2 = (E + PE2 - 1) / PE2;
    agg_edge2<<<(chunks2 + 15) / 16, 256>>>(att2, E);
    finalize2<<<(NN * 32 + 255) / 256, 256>>>(b2, out);

    (void)n_in; (void)out_size;
}

// round 11
// speedup vs baseline: 4.0964x; 1.0914x over previous
#include <cuda_runtime.h>
#include <cstdint>

#define NN 50000
#define EE 800000
#define F1 256      // layer1 hidden (H*C = 8*32)
#define H1 8
#define F2 64       // layer2 output
#define SCAN_B 196  // ceil(50000/256)

// ---------------- static scratch ----------
__device__ float g_xlr1[(size_t)NN * 512];   // [n][0:256)=xl1, [256:512)=xr1
__device__ float g_h1[NN * F1];              // relu(aggr/den + b1)
__device__ float g_xlr2[(size_t)NN * 128];   // [n][0:64)=xl2, [64:128)=xr2

__device__ float g_Bp1[256 * 512];           // Wl1 | Wr1
__device__ float g_Bp2[256 * 128];           // Wl2 | Wr2

// sort scratch (CSR: start(n) = g_pos[n] - g_cnt[n], end(n) = g_pos[n])
__device__ int g_cnt[NN];
__device__ int g_bsum[SCAN_B];
__device__ int g_pos[NN];
__device__ int g_perm[EE];                   // src ids, sorted by dst

__device__ __forceinline__ uint32_t to_tf32(float f) {
    uint32_t o;
    asm("cvt.rna.tf32.f32 %0, %1;" : "=r"(o) : "f"(f));
    return o;
}

// ---------------- init (only histogram counters) ----------------------------
__global__ void init_kernel() {
    int i = blockIdx.x * blockDim.x + threadIdx.x;
    if (i < NN) g_cnt[i] = 0;
}

// ---------------- weight packing: Bp = [Wl | Wr] ----------------------------
__global__ void pack_kernel(const float* __restrict__ Wl, const float* __restrict__ Wr,
                            float* __restrict__ Bp, int K, int Mh) {
    int i = blockIdx.x * blockDim.x + threadIdx.x;
    if (i >= K * Mh) return;
    int k = i / Mh, j = i % Mh;
    Bp[(size_t)k * 2 * Mh + j]      = Wl[i];
    Bp[(size_t)k * 2 * Mh + Mh + j] = Wr[i];
}

// ---------------- counting sort by dst --------------------------------------
__global__ void hist_kernel(const int* __restrict__ ei, int E) {
    int i = blockIdx.x * blockDim.x + threadIdx.x;
    int stride = gridDim.x * blockDim.x;
    for (int e = i; e < E; e += stride)
        atomicAdd(&g_cnt[ei[E + e]], 1);
}

__global__ void scanA_kernel() {
    __shared__ int sh[256];
    int b = blockIdx.x, t = threadIdx.x;
    int i = b * 256 + t;
    int v = (i < NN) ? g_cnt[i] : 0;
    sh[t] = v; __syncthreads();
    for (int off = 128; off; off >>= 1) {
        if (t < off) sh[t] += sh[t + off];
        __syncthreads();
    }
    if (t == 0) g_bsum[b] = sh[0];
}

__global__ void scanB_kernel() {    // exclusive scan of 196 block sums, 1 block
    __shared__ int sh[256];
    int t = threadIdx.x;
    int v = (t < SCAN_B) ? g_bsum[t] : 0;
    sh[t] = v; __syncthreads();
#pragma unroll
    for (int off = 1; off < 256; off <<= 1) {
        int x = (t >= off) ? sh[t - off] : 0;
        __syncthreads();
        sh[t] += x;
        __syncthreads();
    }
    if (t < SCAN_B) g_bsum[t] = sh[t] - v;
}

__global__ void scanC_kernel() {
    __shared__ int sh[256];
    int b = blockIdx.x, t = threadIdx.x;
    int i = b * 256 + t;
    int v = (i < NN) ? g_cnt[i] : 0;
    sh[t] = v; __syncthreads();
#pragma unroll
    for (int off = 1; off < 256; off <<= 1) {
        int x = (t >= off) ? sh[t - off] : 0;
        __syncthreads();
        sh[t] += x;
        __syncthreads();
    }
    if (i < NN) g_pos[i] = g_bsum[b] + sh[t] - v;   // exclusive start
}

__global__ void scatter_kernel(const int* __restrict__ ei, int E) {
    int i = blockIdx.x * blockDim.x + threadIdx.x;
    int stride = gridDim.x * blockDim.x;
    for (int e = i; e < E; e += stride) {
        int s = ei[e], d = ei[E + e];
        int pos = atomicAdd(&g_pos[d], 1);
        g_perm[pos] = s;
    }
    // after this kernel: g_pos[d] = end offset; start = g_pos[d] - g_cnt[d]
}

// ---------------- TF32 tensor GEMM: C[N,M] = A[N,K] @ B[K,M] ----------------
__global__ __launch_bounds__(256) void tf32_gemm(
        const float* __restrict__ A, const float* __restrict__ B,
        float* __restrict__ C, int N, int K, int M) {
    __shared__ uint32_t As[128][18];
    __shared__ uint32_t Bs[16][132];

    int tid = threadIdx.x;
    int lane = tid & 31;
    int wid = tid >> 5;
    int wm = wid >> 2;
    int wn = wid & 3;
    int rowBase = blockIdx.y * 128;
    int colBase = blockIdx.x * 128;

    float c[16][4] = {};
    int l4 = lane >> 2;
    int l3 = lane & 3;

    for (int k0 = 0; k0 < K; k0 += 16) {
#pragma unroll
        for (int i = 0; i < 2; i++) {
            int r = (tid >> 2) + 64 * i;
            int kk = (tid & 3) * 4;
            int grow = rowBase + r;
            float4 v = make_float4(0.f, 0.f, 0.f, 0.f);
            if (grow < N) v = *(const float4*)(A + (size_t)grow * K + k0 + kk);
            As[r][kk + 0] = to_tf32(v.x);
            As[r][kk + 1] = to_tf32(v.y);
            As[r][kk + 2] = to_tf32(v.z);
            As[r][kk + 3] = to_tf32(v.w);
        }
#pragma unroll
        for (int i = 0; i < 2; i++) {
            int kk = (tid >> 5) + 8 * i;
            int cc = (tid & 31) * 4;
            float4 v = *(const float4*)(B + (size_t)(k0 + kk) * M + colBase + cc);
            Bs[kk][cc + 0] = to_tf32(v.x);
            Bs[kk][cc + 1] = to_tf32(v.y);
            Bs[kk][cc + 2] = to_tf32(v.z);
            Bs[kk][cc + 3] = to_tf32(v.w);
        }
        __syncthreads();

#pragma unroll
        for (int ks = 0; ks < 2; ks++) {
            int kb = ks * 8;
            uint32_t af[4][4];
#pragma unroll
            for (int mi = 0; mi < 4; mi++) {
                int r = wm * 64 + mi * 16 + l4;
                af[mi][0] = As[r][kb + l3];
                af[mi][1] = As[r + 8][kb + l3];
                af[mi][2] = As[r][kb + l3 + 4];
                af[mi][3] = As[r + 8][kb + l3 + 4];
            }
            uint32_t bf[4][2];
#pragma unroll
            for (int ni = 0; ni < 4; ni++) {
                int ccol = wn * 32 + ni * 8 + l4;
                bf[ni][0] = Bs[kb + l3][ccol];
                bf[ni][1] = Bs[kb + l3 + 4][ccol];
            }
#pragma unroll
            for (int mi = 0; mi < 4; mi++)
#pragma unroll
                for (int ni = 0; ni < 4; ni++) {
                    float* cr = c[mi * 4 + ni];
                    asm volatile(
                        "mma.sync.aligned.m16n8k8.row.col.f32.tf32.tf32.f32 "
                        "{%0,%1,%2,%3}, {%4,%5,%6,%7}, {%8,%9}, {%0,%1,%2,%3};"
                        : "+f"(cr[0]), "+f"(cr[1]), "+f"(cr[2]), "+f"(cr[3])
                        : "r"(af[mi][0]), "r"(af[mi][1]), "r"(af[mi][2]), "r"(af[mi][3]),
                          "r"(bf[ni][0]), "r"(bf[ni][1]));
                }
        }
        __syncthreads();
    }

#pragma unroll
    for (int mi = 0; mi < 4; mi++) {
        int r0 = rowBase + wm * 64 + mi * 16 + l4;
#pragma unroll
        for (int ni = 0; ni < 4; ni++) {
            int cc = colBase + wn * 32 + ni * 8 + l3 * 2;
            float* cr = c[mi * 4 + ni];
            if (r0 < N)
                *(float2*)(C + (size_t)r0 * M + cc) = make_float2(cr[0], cr[1]);
            if (r0 + 8 < N)
                *(float2*)(C + (size_t)(r0 + 8) * M + cc) = make_float2(cr[2], cr[3]);
        }
    }
}

// ---------------- layer-1: node-centric aggregation + fused finalize --------
// One warp per destination node. Exclusive row ownership: plain stores, no
// atomics, no init. Writes h1 = relu(acc/den + b1) directly.
__global__ void agg_node1(const float* __restrict__ att,
                          const float* __restrict__ b1) {
    int n = (int)((blockIdx.x * blockDim.x + threadIdx.x) >> 5);
    int lane = threadIdx.x & 31;
    if (n >= NN) return;

    int end = g_pos[n];
    int start = end - g_cnt[n];

    const float4* pa = (const float4*)att;
    float4 t0 = pa[lane], t1 = pa[32 + lane];

    const float4* pr = (const float4*)(g_xlr1 + (size_t)n * 512 + 256);
    float4 b0 = pr[lane], b1v = pr[32 + lane];

    float4 acc0 = make_float4(0, 0, 0, 0), acc1 = make_float4(0, 0, 0, 0);
    float dn0 = 0.f, dn1 = 0.f;

    for (int e = start; e < end; e++) {
        int s = g_perm[e];
        const float4* pl = (const float4*)(g_xlr1 + (size_t)s * 512);
        float4 a0 = pl[lane], a1 = pl[32 + lane];

        float v, p0 = 0.f, p1 = 0.f;
        v = a0.x + b0.x;  p0 += (v > 0.f ? v : 0.2f * v) * t0.x;
        v = a0.y + b0.y;  p0 += (v > 0.f ? v : 0.2f * v) * t0.y;
        v = a0.z + b0.z;  p0 += (v > 0.f ? v : 0.2f * v) * t0.z;
        v = a0.w + b0.w;  p0 += (v > 0.f ? v : 0.2f * v) * t0.w;
        v = a1.x + b1v.x; p1 += (v > 0.f ? v : 0.2f * v) * t1.x;
        v = a1.y + b1v.y; p1 += (v > 0.f ? v : 0.2f * v) * t1.y;
        v = a1.z + b1v.z; p1 += (v > 0.f ? v : 0.2f * v) * t1.z;
        v = a1.w + b1v.w; p1 += (v > 0.f ? v : 0.2f * v) * t1.w;

#pragma unroll
        for (int o = 1; o < 8; o <<= 1) {
            p0 += __shfl_xor_sync(0xFFFFFFFFu, p0, o);
            p1 += __shfl_xor_sync(0xFFFFFFFFu, p1, o);
        }
        float e0 = __expf(p0);
        float e1 = __expf(p1);

        acc0.x += a0.x * e0; acc0.y += a0.y * e0; acc0.z += a0.z * e0; acc0.w += a0.w * e0;
        acc1.x += a1.x * e1; acc1.y += a1.y * e1; acc1.z += a1.z * e1; acc1.w += a1.w * e1;
        dn0 += e0; dn1 += e1;
    }

    // finalize: h = relu(acc/den + bias)
    float inv0 = 1.f / (dn0 + 1e-16f);
    float inv1 = 1.f / (dn1 + 1e-16f);
    const float4* pb = (const float4*)b1;
    float4 bb0 = pb[lane], bb1 = pb[32 + lane];
    float4 r0, r1;
    r0.x = fmaxf(acc0.x * inv0 + bb0.x, 0.f);
    r0.y = fmaxf(acc0.y * inv0 + bb0.y, 0.f);
    r0.z = fmaxf(acc0.z * inv0 + bb0.z, 0.f);
    r0.w = fmaxf(acc0.w * inv0 + bb0.w, 0.f);
    r1.x = fmaxf(acc1.x * inv1 + bb1.x, 0.f);
    r1.y = fmaxf(acc1.y * inv1 + bb1.y, 0.f);
    r1.z = fmaxf(acc1.z * inv1 + bb1.z, 0.f);
    r1.w = fmaxf(acc1.w * inv1 + bb1.w, 0.f);
    float4* ph = (float4*)(g_h1 + (size_t)n * F1);
    ph[lane] = r0;
    ph[32 + lane] = r1;
}

// ---------------- layer-2: node-centric + fused bias/log_softmax ------------
// Half-warp per node (16 lanes * float4 = 64 channels). Writes d_out directly.
__global__ void agg_node2(const float* __restrict__ att,
                          const float* __restrict__ b2,
                          float* __restrict__ out) {
    int n = (int)((blockIdx.x * blockDim.x + threadIdx.x) >> 4);
    int l16 = threadIdx.x & 15;
    unsigned hm = 0xFFFFu << (threadIdx.x & 16);
    if (n >= NN) return;

    int end = g_pos[n];
    int start = end - g_cnt[n];

    float4 t = ((const float4*)att)[l16];
    float4 b = ((const float4*)(g_xlr2 + (size_t)n * 128 + 64))[l16];

    float4 acc = make_float4(0, 0, 0, 0);
    float dn = 0.f;

    for (int e = start; e < end; e++) {
        int s = g_perm[e];
        float4 a = ((const float4*)(g_xlr2 + (size_t)s * 128))[l16];

        float v, p = 0.f;
        v = a.x + b.x; p += (v > 0.f ? v : 0.2f * v) * t.x;
        v = a.y + b.y; p += (v > 0.f ? v : 0.2f * v) * t.y;
        v = a.z + b.z; p += (v > 0.f ? v : 0.2f * v) * t.z;
        v = a.w + b.w; p += (v > 0.f ? v : 0.2f * v) * t.w;

#pragma unroll
        for (int o = 1; o < 16; o <<= 1) p += __shfl_xor_sync(hm, p, o);
        float ex = __expf(p);

        acc.x += a.x * ex; acc.y += a.y * ex; acc.z += a.z * ex; acc.w += a.w * ex;
        dn += ex;
    }

    float inv = 1.f / (dn + 1e-16f);
    float4 bb = ((const float4*)b2)[l16];
    float4 vv;
    vv.x = acc.x * inv + bb.x;
    vv.y = acc.y * inv + bb.y;
    vv.z = acc.z * inv + bb.z;
    vv.w = acc.w * inv + bb.w;

    // log_softmax over the 64 channels held by this half-warp
    float mx = fmaxf(fmaxf(vv.x, vv.y), fmaxf(vv.z, vv.w));
#pragma unroll
    for (int o = 1; o < 16; o <<= 1) mx = fmaxf(mx, __shfl_xor_sync(hm, mx, o));
    float se = __expf(vv.x - mx) + __expf(vv.y - mx) + __expf(vv.z - mx) + __expf(vv.w - mx);
#pragma unroll
    for (int o = 1; o < 16; o <<= 1) se += __shfl_xor_sync(hm, se, o);
    float lse = mx + __logf(se);

    ((float4*)(out + (size_t)n * F2))[l16] = vv;
    float4 ls;
    ls.x = vv.x - lse; ls.y = vv.y - lse; ls.z = vv.z - lse; ls.w = vv.w - lse;
    ((float4*)(out + (size_t)NN * F2 + (size_t)n * F2))[l16] = ls;
}

// ---------------- launch ----------------------------------------------------
extern "C" void kernel_launch(void* const* d_in, const int* in_sizes, int n_in,
                              void* d_out, int out_size) {
    const float* x    = (const float*)d_in[0];
    const int*   ei   = (const int*)d_in[1];     // JAX canonicalizes int64 -> int32
    const float* Wl1  = (const float*)d_in[2];
    const float* Wr1  = (const float*)d_in[3];
    const float* att1 = (const float*)d_in[4];
    const float* b1   = (const float*)d_in[5];
    const float* Wl2  = (const float*)d_in[6];
    const float* Wr2  = (const float*)d_in[7];
    const float* att2 = (const float*)d_in[8];
    const float* b2   = (const float*)d_in[9];
    float* out = (float*)d_out;

    int E = in_sizes[1] / 2;
    if (E > EE) E = EE;
    int N = in_sizes[0] / F1;
    if (N > NN) N = NN;

    void *xlr1p, *xlr2p, *h1p, *bp1p, *bp2p;
    cudaGetSymbolAddress(&xlr1p, g_xlr1);
    cudaGetSymbolAddress(&xlr2p, g_xlr2);
    cudaGetSymbolAddress(&h1p,  g_h1);
    cudaGetSymbolAddress(&bp1p, g_Bp1);
    cudaGetSymbolAddress(&bp2p, g_Bp2);

    static cudaStream_t sA = nullptr, sB = nullptr;
    static cudaEvent_t ev0 = nullptr, evS = nullptr, evG = nullptr;
    if (!sA) {
        cudaStreamCreateWithFlags(&sA, cudaStreamNonBlocking);
        cudaStreamCreateWithFlags(&sB, cudaStreamNonBlocking);
        cudaEventCreateWithFlags(&ev0, cudaEventDisableTiming);
        cudaEventCreateWithFlags(&evS, cudaEventDisableTiming);
        cudaEventCreateWithFlags(&evG, cudaEventDisableTiming);
    }

    // fork
    cudaEventRecord(ev0, 0);
    cudaStreamWaitEvent(sA, ev0, 0);
    cudaStreamWaitEvent(sB, ev0, 0);

    // stream A: CSR build (counting sort by dst)
    init_kernel<<<(NN + 255) / 256, 256, 0, sA>>>();
    hist_kernel<<<1024, 256, 0, sA>>>(ei, E);
    scanA_kernel<<<SCAN_B, 256, 0, sA>>>();
    scanB_kernel<<<1, 256, 0, sA>>>();
    scanC_kernel<<<SCAN_B, 256, 0, sA>>>();
    scatter_kernel<<<1024, 256, 0, sA>>>(ei, E);
    cudaEventRecord(evS, sA);

    // stream B: weight packing + layer-1 projection [N,256]@[256,512]
    pack_kernel<<<(256 * 256 + 255) / 256, 256, 0, sB>>>(Wl1, Wr1, (float*)bp1p, 256, 256);
    pack_kernel<<<(256 * 64 + 255) / 256, 256, 0, sB>>>(Wl2, Wr2, (float*)bp2p, 256, 64);
    dim3 grid1(512 / 128, (N + 127) / 128);
    tf32_gemm<<<grid1, 256, 0, sB>>>(x, (const float*)bp1p, (float*)xlr1p, N, F1, 512);
    cudaEventRecord(evG, sB);

    // join
    cudaStreamWaitEvent(0, evS, 0);
    cudaStreamWaitEvent(0, evG, 0);

    // layer-1 aggregation (node-centric, fused finalize -> h1)
    agg_node1<<<(NN + 7) / 8, 256>>>(att1, b1);

    // layer-2 projection: [N,256]@[256,128] on h1 -> xlr2
    dim3 grid2(1, (N + 127) / 128);
    tf32_gemm<<<grid2, 256>>>((const float*)h1p, (const float*)bp2p, (float*)xlr2p, N, F1, 128);

    // layer-2 aggregation + bias + log_softmax -> out
    agg_node2<<<(NN + 15) / 16, 256>>>(att2, b2, out);

    (void)n_in; (void)out_size;
}

// round 13
// speedup vs baseline: 4.7498x; 1.1595x over previous
#include <cuda_runtime.h>
#include <cstdint>

#define NN 50000
#define EE 800000
#define F1 256      // layer1 hidden (H*C = 8*32)
#define H1 8
#define F2 64       // layer2 output
#define SCAN_B 196  // ceil(50000/256)

// ---------------- static scratch ----------
__device__ float g_xlr1[(size_t)NN * 512];   // [n][0:256)=xl1, [256:512)=xr1
__device__ float g_h1[NN * F1];              // relu(aggr/den + b1)
__device__ float g_xlr2[(size_t)NN * 128];   // [n][0:64)=xl2, [64:128)=xr2

__device__ float g_Bp1[256 * 512];           // Wl1 | Wr1
__device__ float g_Bp2[256 * 128];           // Wl2 | Wr2

// sort scratch (CSR: start(n) = g_pos[n] - g_cnt[n], end(n) = g_pos[n])
__device__ int g_cnt[NN];
__device__ int g_bsum[SCAN_B];
__device__ int g_pos[NN];
__device__ int g_perm[EE];                   // src ids, sorted by dst

__device__ __forceinline__ uint32_t to_tf32(float f) {
    uint32_t o;
    asm("cvt.rna.tf32.f32 %0, %1;" : "=r"(o) : "f"(f));
    return o;
}
__device__ __forceinline__ void cp_async16(uint32_t smem_dst, const void* gmem_src, int src_bytes) {
    asm volatile("cp.async.cg.shared.global [%0], [%1], 16, %2;"
                 :: "r"(smem_dst), "l"(gmem_src), "r"(src_bytes));
}
__device__ __forceinline__ void cp_commit() {
    asm volatile("cp.async.commit_group;");
}
template <int N>
__device__ __forceinline__ void cp_wait() {
    asm volatile("cp.async.wait_group %0;" :: "n"(N));
}

// ---------------- init (only histogram counters) ----------------------------
__global__ void init_kernel() {
    int i = blockIdx.x * blockDim.x + threadIdx.x;
    if (i < NN) g_cnt[i] = 0;
}

// ---------------- weight packing: Bp = [Wl | Wr] ----------------------------
__global__ void pack_kernel(const float* __restrict__ Wl, const float* __restrict__ Wr,
                            float* __restrict__ Bp, int K, int Mh) {
    int i = blockIdx.x * blockDim.x + threadIdx.x;
    if (i >= K * Mh) return;
    int k = i / Mh, j = i % Mh;
    Bp[(size_t)k * 2 * Mh + j]      = Wl[i];
    Bp[(size_t)k * 2 * Mh + Mh + j] = Wr[i];
}

// ---------------- counting sort by dst --------------------------------------
__global__ void hist_kernel(const int* __restrict__ ei, int E) {
    int i = blockIdx.x * blockDim.x + threadIdx.x;
    int stride = gridDim.x * blockDim.x;
    for (int e = i; e < E; e += stride)
        atomicAdd(&g_cnt[ei[E + e]], 1);
}

__global__ void scanA_kernel() {
    __shared__ int sh[256];
    int b = blockIdx.x, t = threadIdx.x;
    int i = b * 256 + t;
    int v = (i < NN) ? g_cnt[i] : 0;
    sh[t] = v; __syncthreads();
    for (int off = 128; off; off >>= 1) {
        if (t < off) sh[t] += sh[t + off];
        __syncthreads();
    }
    if (t == 0) g_bsum[b] = sh[0];
}

__global__ void scanB_kernel() {
    __shared__ int sh[256];
    int t = threadIdx.x;
    int v = (t < SCAN_B) ? g_bsum[t] : 0;
    sh[t] = v; __syncthreads();
#pragma unroll
    for (int off = 1; off < 256; off <<= 1) {
        int x = (t >= off) ? sh[t - off] : 0;
        __syncthreads();
        sh[t] += x;
        __syncthreads();
    }
    if (t < SCAN_B) g_bsum[t] = sh[t] - v;
}

__global__ void scanC_kernel() {
    __shared__ int sh[256];
    int b = blockIdx.x, t = threadIdx.x;
    int i = b * 256 + t;
    int v = (i < NN) ? g_cnt[i] : 0;
    sh[t] = v; __syncthreads();
#pragma unroll
    for (int off = 1; off < 256; off <<= 1) {
        int x = (t >= off) ? sh[t - off] : 0;
        __syncthreads();
        sh[t] += x;
        __syncthreads();
    }
    if (i < NN) g_pos[i] = g_bsum[b] + sh[t] - v;
}

__global__ void scatter_kernel(const int* __restrict__ ei, int E) {
    int i = blockIdx.x * blockDim.x + threadIdx.x;
    int stride = gridDim.x * blockDim.x;
    for (int e = i; e < E; e += stride) {
        int s = ei[e], d = ei[E + e];
        int pos = atomicAdd(&g_pos[d], 1);
        g_perm[pos] = s;
    }
}

// ---------------- TF32 tensor GEMM, cp.async double-buffered ----------------
// C[N,M] = A[N,K] @ B[K,M]. Block 128x128, BK=16, 8 warps (2x4),
// warp tile 64x32, fp32 accumulate. tf32 convert on fragment load.
__global__ __launch_bounds__(256) void tf32_gemm(
        const float* __restrict__ A, const float* __restrict__ B,
        float* __restrict__ C, int N, int K, int M) {
    __shared__ float As[2][128][20];     // row stride 80B (16B aligned)
    __shared__ float Bs[2][16][132];     // row stride 528B (16B aligned)

    int tid = threadIdx.x;
    int lane = tid & 31;
    int wid = tid >> 5;
    int wm = wid >> 2;
    int wn = wid & 3;
    int rowBase = blockIdx.y * 128;
    int colBase = blockIdx.x * 128;

    uint32_t sA = (uint32_t)__cvta_generic_to_shared(&As[0][0][0]);
    uint32_t sB = (uint32_t)__cvta_generic_to_shared(&Bs[0][0][0]);

    int ar = tid >> 2;            // 0..63
    int akk = (tid & 3) * 4;      // 0,4,8,12
    int bkk = tid >> 5;           // 0..7
    int bcc = (tid & 31) * 4;     // 0..124

    auto loadTiles = [&](int buf, int k0) {
#pragma unroll
        for (int i = 0; i < 2; i++) {
            int r = ar + 64 * i;
            int grow = rowBase + r;
            const float* src = A + (size_t)grow * K + k0 + akk;
            uint32_t dst = sA + (uint32_t)(((buf * 128 + r) * 20 + akk) * 4);
            cp_async16(dst, src, grow < N ? 16 : 0);
        }
#pragma unroll
        for (int i = 0; i < 2; i++) {
            int kk = bkk + 8 * i;
            const float* src = B + (size_t)(k0 + kk) * M + colBase + bcc;
            uint32_t dst = sB + (uint32_t)(((buf * 16 + kk) * 132 + bcc) * 4);
            cp_async16(dst, src, 16);
        }
        cp_commit();
    };

    float c[16][4] = {};
    int l4 = lane >> 2;
    int l3 = lane & 3;

    loadTiles(0, 0);

    for (int k0 = 0; k0 < K; k0 += 16) {
        int buf = (k0 >> 4) & 1;
        bool more = (k0 + 16) < K;
        if (more) loadTiles(buf ^ 1, k0 + 16);
        if (more) cp_wait<1>(); else cp_wait<0>();
        __syncthreads();

#pragma unroll
        for (int ks = 0; ks < 2; ks++) {
            int kb = ks * 8;
            uint32_t af[4][4];
#pragma unroll
            for (int mi = 0; mi < 4; mi++) {
                int r = wm * 64 + mi * 16 + l4;
                af[mi][0] = to_tf32(As[buf][r][kb + l3]);
                af[mi][1] = to_tf32(As[buf][r + 8][kb + l3]);
                af[mi][2] = to_tf32(As[buf][r][kb + l3 + 4]);
                af[mi][3] = to_tf32(As[buf][r + 8][kb + l3 + 4]);
            }
            uint32_t bf[4][2];
#pragma unroll
            for (int ni = 0; ni < 4; ni++) {
                int ccol = wn * 32 + ni * 8 + l4;
                bf[ni][0] = to_tf32(Bs[buf][kb + l3][ccol]);
                bf[ni][1] = to_tf32(Bs[buf][kb + l3 + 4][ccol]);
            }
#pragma unroll
            for (int mi = 0; mi < 4; mi++)
#pragma unroll
                for (int ni = 0; ni < 4; ni++) {
                    float* cr = c[mi * 4 + ni];
                    asm volatile(
                        "mma.sync.aligned.m16n8k8.row.col.f32.tf32.tf32.f32 "
                        "{%0,%1,%2,%3}, {%4,%5,%6,%7}, {%8,%9}, {%0,%1,%2,%3};"
                        : "+f"(cr[0]), "+f"(cr[1]), "+f"(cr[2]), "+f"(cr[3])
                        : "r"(af[mi][0]), "r"(af[mi][1]), "r"(af[mi][2]), "r"(af[mi][3]),
                          "r"(bf[ni][0]), "r"(bf[ni][1]));
                }
        }
        __syncthreads();   // all warps done with buf before next prefetch overwrites it
    }

#pragma unroll
    for (int mi = 0; mi < 4; mi++) {
        int r0 = rowBase + wm * 64 + mi * 16 + l4;
#pragma unroll
        for (int ni = 0; ni < 4; ni++) {
            int cc = colBase + wn * 32 + ni * 8 + l3 * 2;
            float* cr = c[mi * 4 + ni];
            if (r0 < N)
                *(float2*)(C + (size_t)r0 * M + cc) = make_float2(cr[0], cr[1]);
            if (r0 + 8 < N)
                *(float2*)(C + (size_t)(r0 + 8) * M + cc) = make_float2(cr[2], cr[3]);
        }
    }
}

// ---------------- layer-1: node-centric aggregation, 2-edge unrolled --------
__global__ void agg_node1(const float* __restrict__ att,
                          const float* __restrict__ b1) {
    int n = (int)((blockIdx.x * blockDim.x + threadIdx.x) >> 5);
    int lane = threadIdx.x & 31;
    if (n >= NN) return;

    int end = g_pos[n];
    int start = end - g_cnt[n];

    const float4* pa = (const float4*)att;
    float4 t0 = pa[lane], t1 = pa[32 + lane];

    const float4* pr = (const float4*)(g_xlr1 + (size_t)n * 512 + 256);
    float4 b0 = pr[lane], b1v = pr[32 + lane];

    float4 acc0 = make_float4(0, 0, 0, 0), acc1 = make_float4(0, 0, 0, 0);
    float dn0 = 0.f, dn1 = 0.f;

    int e = start;
    for (; e + 1 < end; e += 2) {
        int s0 = g_perm[e];
        int s1 = g_perm[e + 1];
        const float4* pl0 = (const float4*)(g_xlr1 + (size_t)s0 * 512);
        const float4* pl1 = (const float4*)(g_xlr1 + (size_t)s1 * 512);
        float4 x00 = pl0[lane], x01 = pl0[32 + lane];
        float4 x10 = pl1[lane], x11 = pl1[32 + lane];

        float v, pA0 = 0.f, pA1 = 0.f, pB0 = 0.f, pB1 = 0.f;
        v = x00.x + b0.x;  pA0 += (v > 0.f ? v : 0.2f * v) * t0.x;
        v = x00.y + b0.y;  pA0 += (v > 0.f ? v : 0.2f * v) * t0.y;
        v = x00.z + b0.z;  pA0 += (v > 0.f ? v : 0.2f * v) * t0.z;
        v = x00.w + b0.w;  pA0 += (v > 0.f ? v : 0.2f * v) * t0.w;
        v = x01.x + b1v.x; pA1 += (v > 0.f ? v : 0.2f * v) * t1.x;
        v = x01.y + b1v.y; pA1 += (v > 0.f ? v : 0.2f * v) * t1.y;
        v = x01.z + b1v.z; pA1 += (v > 0.f ? v : 0.2f * v) * t1.z;
        v = x01.w + b1v.w; pA1 += (v > 0.f ? v : 0.2f * v) * t1.w;
        v = x10.x + b0.x;  pB0 += (v > 0.f ? v : 0.2f * v) * t0.x;
        v = x10.y + b0.y;  pB0 += (v > 0.f ? v : 0.2f * v) * t0.y;
        v = x10.z + b0.z;  pB0 += (v > 0.f ? v : 0.2f * v) * t0.z;
        v = x10.w + b0.w;  pB0 += (v > 0.f ? v : 0.2f * v) * t0.w;
        v = x11.x + b1v.x; pB1 += (v > 0.f ? v : 0.2f * v) * t1.x;
        v = x11.y + b1v.y; pB1 += (v > 0.f ? v : 0.2f * v) * t1.y;
        v = x11.z + b1v.z; pB1 += (v > 0.f ? v : 0.2f * v) * t1.z;
        v = x11.w + b1v.w; pB1 += (v > 0.f ? v : 0.2f * v) * t1.w;

#pragma unroll
        for (int o = 1; o < 8; o <<= 1) {
            pA0 += __shfl_xor_sync(0xFFFFFFFFu, pA0, o);
            pA1 += __shfl_xor_sync(0xFFFFFFFFu, pA1, o);
            pB0 += __shfl_xor_sync(0xFFFFFFFFu, pB0, o);
            pB1 += __shfl_xor_sync(0xFFFFFFFFu, pB1, o);
        }
        float eA0 = __expf(pA0), eA1 = __expf(pA1);
        float eB0 = __expf(pB0), eB1 = __expf(pB1);

        acc0.x += x00.x * eA0 + x10.x * eB0;
        acc0.y += x00.y * eA0 + x10.y * eB0;
        acc0.z += x00.z * eA0 + x10.z * eB0;
        acc0.w += x00.w * eA0 + x10.w * eB0;
        acc1.x += x01.x * eA1 + x11.x * eB1;
        acc1.y += x01.y * eA1 + x11.y * eB1;
        acc1.z += x01.z * eA1 + x11.z * eB1;
        acc1.w += x01.w * eA1 + x11.w * eB1;
        dn0 += eA0 + eB0;
        dn1 += eA1 + eB1;
    }
    if (e < end) {
        int s = g_perm[e];
        const float4* pl = (const float4*)(g_xlr1 + (size_t)s * 512);
        float4 a0 = pl[lane], a1 = pl[32 + lane];

        float v, p0 = 0.f, p1 = 0.f;
        v = a0.x + b0.x;  p0 += (v > 0.f ? v : 0.2f * v) * t0.x;
        v = a0.y + b0.y;  p0 += (v > 0.f ? v : 0.2f * v) * t0.y;
        v = a0.z + b0.z;  p0 += (v > 0.f ? v : 0.2f * v) * t0.z;
        v = a0.w + b0.w;  p0 += (v > 0.f ? v : 0.2f * v) * t0.w;
        v = a1.x + b1v.x; p1 += (v > 0.f ? v : 0.2f * v) * t1.x;
        v = a1.y + b1v.y; p1 += (v > 0.f ? v : 0.2f * v) * t1.y;
        v = a1.z + b1v.z; p1 += (v > 0.f ? v : 0.2f * v) * t1.z;
        v = a1.w + b1v.w; p1 += (v > 0.f ? v : 0.2f * v) * t1.w;
#pragma unroll
        for (int o = 1; o < 8; o <<= 1) {
            p0 += __shfl_xor_sync(0xFFFFFFFFu, p0, o);
            p1 += __shfl_xor_sync(0xFFFFFFFFu, p1, o);
        }
        float e0 = __expf(p0), e1 = __expf(p1);
        acc0.x += a0.x * e0; acc0.y += a0.y * e0; acc0.z += a0.z * e0; acc0.w += a0.w * e0;
        acc1.x += a1.x * e1; acc1.y += a1.y * e1; acc1.z += a1.z * e1; acc1.w += a1.w * e1;
        dn0 += e0; dn1 += e1;
    }

    float inv0 = 1.f / (dn0 + 1e-16f);
    float inv1 = 1.f / (dn1 + 1e-16f);
    const float4* pb = (const float4*)b1;
    float4 bb0 = pb[lane], bb1 = pb[32 + lane];
    float4 r0, r1;
    r0.x = fmaxf(acc0.x * inv0 + bb0.x, 0.f);
    r0.y = fmaxf(acc0.y * inv0 + bb0.y, 0.f);
    r0.z = fmaxf(acc0.z * inv0 + bb0.z, 0.f);
    r0.w = fmaxf(acc0.w * inv0 + bb0.w, 0.f);
    r1.x = fmaxf(acc1.x * inv1 + bb1.x, 0.f);
    r1.y = fmaxf(acc1.y * inv1 + bb1.y, 0.f);
    r1.z = fmaxf(acc1.z * inv1 + bb1.z, 0.f);
    r1.w = fmaxf(acc1.w * inv1 + bb1.w, 0.f);
    float4* ph = (float4*)(g_h1 + (size_t)n * F1);
    ph[lane] = r0;
    ph[32 + lane] = r1;
}

// ---------------- layer-2: node-centric, 2-edge unrolled --------------------
__global__ void agg_node2(const float* __restrict__ att,
                          const float* __restrict__ b2,
                          float* __restrict__ out) {
    int n = (int)((blockIdx.x * blockDim.x + threadIdx.x) >> 4);
    int l16 = threadIdx.x & 15;
    unsigned hm = 0xFFFFu << (threadIdx.x & 16);
    if (n >= NN) return;

    int end = g_pos[n];
    int start = end - g_cnt[n];

    float4 t = ((const float4*)att)[l16];
    float4 b = ((const float4*)(g_xlr2 + (size_t)n * 128 + 64))[l16];

    float4 acc = make_float4(0, 0, 0, 0);
    float dn = 0.f;

    int e = start;
    for (; e + 1 < end; e += 2) {
        int s0 = g_perm[e];
        int s1 = g_perm[e + 1];
        float4 a0 = ((const float4*)(g_xlr2 + (size_t)s0 * 128))[l16];
        float4 a1 = ((const float4*)(g_xlr2 + (size_t)s1 * 128))[l16];

        float v, p0 = 0.f, p1 = 0.f;
        v = a0.x + b.x; p0 += (v > 0.f ? v : 0.2f * v) * t.x;
        v = a0.y + b.y; p0 += (v > 0.f ? v : 0.2f * v) * t.y;
        v = a0.z + b.z; p0 += (v > 0.f ? v : 0.2f * v) * t.z;
        v = a0.w + b.w; p0 += (v > 0.f ? v : 0.2f * v) * t.w;
        v = a1.x + b.x; p1 += (v > 0.f ? v : 0.2f * v) * t.x;
        v = a1.y + b.y; p1 += (v > 0.f ? v : 0.2f * v) * t.y;
        v = a1.z + b.z; p1 += (v > 0.f ? v : 0.2f * v) * t.z;
        v = a1.w + b.w; p1 += (v > 0.f ? v : 0.2f * v) * t.w;

#pragma unroll
        for (int o = 1; o < 16; o <<= 1) {
            p0 += __shfl_xor_sync(hm, p0, o);
            p1 += __shfl_xor_sync(hm, p1, o);
        }
        float e0 = __expf(p0), e1 = __expf(p1);

        acc.x += a0.x * e0 + a1.x * e1;
        acc.y += a0.y * e0 + a1.y * e1;
        acc.z += a0.z * e0 + a1.z * e1;
        acc.w += a0.w * e0 + a1.w * e1;
        dn += e0 + e1;
    }
    if (e < end) {
        int s = g_perm[e];
        float4 a = ((const float4*)(g_xlr2 + (size_t)s * 128))[l16];
        float v, p = 0.f;
        v = a.x + b.x; p += (v > 0.f ? v : 0.2f * v) * t.x;
        v = a.y + b.y; p += (v > 0.f ? v : 0.2f * v) * t.y;
        v = a.z + b.z; p += (v > 0.f ? v : 0.2f * v) * t.z;
        v = a.w + b.w; p += (v > 0.f ? v : 0.2f * v) * t.w;
#pragma unroll
        for (int o = 1; o < 16; o <<= 1) p += __shfl_xor_sync(hm, p, o);
        float ex = __expf(p);
        acc.x += a.x * ex; acc.y += a.y * ex; acc.z += a.z * ex; acc.w += a.w * ex;
        dn += ex;
    }

    float inv = 1.f / (dn + 1e-16f);
    float4 bb = ((const float4*)b2)[l16];
    float4 vv;
    vv.x = acc.x * inv + bb.x;
    vv.y = acc.y * inv + bb.y;
    vv.z = acc.z * inv + bb.z;
    vv.w = acc.w * inv + bb.w;

    float mx = fmaxf(fmaxf(vv.x, vv.y), fmaxf(vv.z, vv.w));
#pragma unroll
    for (int o = 1; o < 16; o <<= 1) mx = fmaxf(mx, __shfl_xor_sync(hm, mx, o));
    float se = __expf(vv.x - mx) + __expf(vv.y - mx) + __expf(vv.z - mx) + __expf(vv.w - mx);
#pragma unroll
    for (int o = 1; o < 16; o <<= 1) se += __shfl_xor_sync(hm, se, o);
    float lse = mx + __logf(se);

    ((float4*)(out + (size_t)n * F2))[l16] = vv;
    float4 ls;
    ls.x = vv.x - lse; ls.y = vv.y - lse; ls.z = vv.z - lse; ls.w = vv.w - lse;
    ((float4*)(out + (size_t)NN * F2 + (size_t)n * F2))[l16] = ls;
}

// ---------------- launch ----------------------------------------------------
extern "C" void kernel_launch(void* const* d_in, const int* in_sizes, int n_in,
                              void* d_out, int out_size) {
    const float* x    = (const float*)d_in[0];
    const int*   ei   = (const int*)d_in[1];     // JAX canonicalizes int64 -> int32
    const float* Wl1  = (const float*)d_in[2];
    const float* Wr1  = (const float*)d_in[3];
    const float* att1 = (const float*)d_in[4];
    const float* b1   = (const float*)d_in[5];
    const float* Wl2  = (const float*)d_in[6];
    const float* Wr2  = (const float*)d_in[7];
    const float* att2 = (const float*)d_in[8];
    const float* b2   = (const float*)d_in[9];
    float* out = (float*)d_out;

    int E = in_sizes[1] / 2;
    if (E > EE) E = EE;
    int N = in_sizes[0] / F1;
    if (N > NN) N = NN;

    void *xlr1p, *xlr2p, *h1p, *bp1p, *bp2p;
    cudaGetSymbolAddress(&xlr1p, g_xlr1);
    cudaGetSymbolAddress(&xlr2p, g_xlr2);
    cudaGetSymbolAddress(&h1p,  g_h1);
    cudaGetSymbolAddress(&bp1p, g_Bp1);
    cudaGetSymbolAddress(&bp2p, g_Bp2);

    static cudaStream_t sA = nullptr, sB = nullptr;
    static cudaEvent_t ev0 = nullptr, evS = nullptr, evG = nullptr;
    if (!sA) {
        cudaStreamCreateWithFlags(&sA, cudaStreamNonBlocking);
        cudaStreamCreateWithFlags(&sB, cudaStreamNonBlocking);
        cudaEventCreateWithFlags(&ev0, cudaEventDisableTiming);
        cudaEventCreateWithFlags(&evS, cudaEventDisableTiming);
        cudaEventCreateWithFlags(&evG, cudaEventDisableTiming);
    }

    // fork
    cudaEventRecord(ev0, 0);
    cudaStreamWaitEvent(sA, ev0, 0);
    cudaStreamWaitEvent(sB, ev0, 0);

    // stream A: CSR build (counting sort by dst)
    init_kernel<<<(NN + 255) / 256, 256, 0, sA>>>();
    hist_kernel<<<1024, 256, 0, sA>>>(ei, E);
    scanA_kernel<<<SCAN_B, 256, 0, sA>>>();
    scanB_kernel<<<1, 256, 0, sA>>>();
    scanC_kernel<<<SCAN_B, 256, 0, sA>>>();
    scatter_kernel<<<1024, 256, 0, sA>>>(ei, E);
    cudaEventRecord(evS, sA);

    // stream B: weight packing + layer-1 projection [N,256]@[256,512]
    pack_kernel<<<(256 * 256 + 255) / 256, 256, 0, sB>>>(Wl1, Wr1, (float*)bp1p, 256, 256);
    pack_kernel<<<(256 * 64 + 255) / 256, 256, 0, sB>>>(Wl2, Wr2, (float*)bp2p, 256, 64);
    dim3 grid1(512 / 128, (N + 127) / 128);
    tf32_gemm<<<grid1, 256, 0, sB>>>(x, (const float*)bp1p, (float*)xlr1p, N, F1, 512);
    cudaEventRecord(evG, sB);

    // join
    cudaStreamWaitEvent(0, evS, 0);
    cudaStreamWaitEvent(0, evG, 0);

    // layer-1 aggregation (node-centric, fused finalize -> h1)
    agg_node1<<<(NN + 7) / 8, 256>>>(att1, b1);

    // layer-2 projection: [N,256]@[256,128] on h1 -> xlr2
    dim3 grid2(1, (N + 127) / 128);
    tf32_gemm<<<grid2, 256>>>((const float*)h1p, (const float*)bp2p, (float*)xlr2p, N, F1, 128);

    // layer-2 aggregation + bias + log_softmax -> out
    agg_node2<<<(NN + 15) / 16, 256>>>(att2, b2, out);

    (void)n_in; (void)out_size;
}